// round 2
// baseline (speedup 1.0000x reference)
#include <cuda_runtime.h>
#include <math.h>

// Problem constants
#define B_   4
#define S_   2048
#define E_   2048
#define H_   16
#define D_   128
#define MTOT (B_ * S_)            // 8192 rows for all projections

// NOISE_SCALE = sqrt(2*ln(1.25/1e-5)) = sqrt(23.4721423...) = 4.84480515...
#define NSCALE 4.84480515f
#define ATTN_SCALE 0.08838834764831845f   // 1/sqrt(128)

// ---------------------------------------------------------------------------
// Scratch (allocation-free rule: __device__ globals)
// ---------------------------------------------------------------------------
__device__ float g_q[(size_t)MTOT * E_];
__device__ float g_k[(size_t)MTOT * E_];
__device__ float g_v[(size_t)MTOT * E_];
__device__ float g_ctx[(size_t)MTOT * E_];

// ---------------------------------------------------------------------------
// GEMM-NT + bias:  out[m,n] = sum_k X[m,k] * W[n,k] + bias[n]
// X: [M,K] row-major, W: [N,K] row-major. Tiles 128x128x8, 256 threads,
// 8x8 micro-tile per thread with split rows/cols (r, r+64) to keep shared
// loads at <=2-way conflicts.
// ---------------------------------------------------------------------------
__global__ __launch_bounds__(256, 2)
void gemm_nt_bias_kernel(const float* __restrict__ X,
                         const float* __restrict__ W,
                         const float* __restrict__ bias,
                         float* __restrict__ out,
                         int M, int N, int K)
{
    __shared__ float As[8][132];   // As[k][row]
    __shared__ float Bs[8][132];   // Bs[k][col]

    const int tid = threadIdx.x;
    const int tx = tid & 15;
    const int ty = tid >> 4;
    const int m0 = blockIdx.y * 128;
    const int n0 = blockIdx.x * 128;

    const int lrow = tid >> 1;          // 0..127
    const int lk   = (tid & 1) * 4;     // 0 or 4

    const float* Ap = X + (size_t)(m0 + lrow) * K + lk;
    const float* Bp = W + (size_t)(n0 + lrow) * K + lk;

    float acc[8][8];
#pragma unroll
    for (int i = 0; i < 8; i++)
#pragma unroll
        for (int j = 0; j < 8; j++) acc[i][j] = 0.0f;

    float4 a4 = *(const float4*)Ap;
    float4 b4 = *(const float4*)Bp;

    for (int k0 = 0; k0 < K; k0 += 8) {
        __syncthreads();
        As[lk + 0][lrow] = a4.x; As[lk + 1][lrow] = a4.y;
        As[lk + 2][lrow] = a4.z; As[lk + 3][lrow] = a4.w;
        Bs[lk + 0][lrow] = b4.x; Bs[lk + 1][lrow] = b4.y;
        Bs[lk + 2][lrow] = b4.z; Bs[lk + 3][lrow] = b4.w;
        __syncthreads();

        if (k0 + 8 < K) {           // prefetch next slab while computing
            a4 = *(const float4*)(Ap + k0 + 8);
            b4 = *(const float4*)(Bp + k0 + 8);
        }

#pragma unroll
        for (int kk = 0; kk < 8; kk++) {
            float a[8], b[8];
            *(float4*)&a[0] = *(const float4*)&As[kk][ty * 4];
            *(float4*)&a[4] = *(const float4*)&As[kk][64 + ty * 4];
            *(float4*)&b[0] = *(const float4*)&Bs[kk][tx * 4];
            *(float4*)&b[4] = *(const float4*)&Bs[kk][64 + tx * 4];
#pragma unroll
            for (int i = 0; i < 8; i++)
#pragma unroll
                for (int j = 0; j < 8; j++)
                    acc[i][j] += a[i] * b[j];
        }
    }

    // bias (same 8 cols for all 8 rows)
    float bb[8];
#pragma unroll
    for (int j = 0; j < 4; j++) {
        bb[j]     = bias[n0 + tx * 4 + j];
        bb[4 + j] = bias[n0 + 64 + tx * 4 + j];
    }

#pragma unroll
    for (int i = 0; i < 8; i++) {
        const int r = (i < 4) ? (ty * 4 + i) : (64 + ty * 4 + (i - 4));
        float* orow = out + (size_t)(m0 + r) * N + n0;
#pragma unroll
        for (int jg = 0; jg < 2; jg++) {
            const int c = (jg == 0) ? (tx * 4) : (64 + tx * 4);
            float4 w4;
            w4.x = acc[i][jg * 4 + 0] + bb[jg * 4 + 0];
            w4.y = acc[i][jg * 4 + 1] + bb[jg * 4 + 1];
            w4.z = acc[i][jg * 4 + 2] + bb[jg * 4 + 2];
            w4.w = acc[i][jg * 4 + 3] + bb[jg * 4 + 3];
            *(float4*)(orow + c) = w4;
        }
    }
}

// ---------------------------------------------------------------------------
// Flash attention (fp32, online softmax) + fused DP noise into ctx.
// Grid: (S/64, H, B). Block: 256 threads. One (b,h) x 64-query tile per block.
// K tile is stored TRANSPOSED in smem (Kt[d][kv]) so the QK^T inner loop is
// conflict-free; V stays natural (Vs[kv][d]).
// ---------------------------------------------------------------------------
#define BQ   64
#define BKV  64
#define QLD  132   // Qs row stride (floats)
#define KLD  68    // Kt row stride
#define VLD  132   // Vs row stride
#define SLD  68    // Ss row stride

#define ATTN_SMEM_FLOATS (BQ*QLD + D_*KLD + BKV*VLD + BQ*SLD + 3*BQ)
#define ATTN_SMEM_BYTES  (ATTN_SMEM_FLOATS * 4)

__global__ __launch_bounds__(256, 1)
void flash_attn_kernel(const float* __restrict__ Qg,
                       const float* __restrict__ Kg,
                       const float* __restrict__ Vg,
                       const float* __restrict__ Ng,
                       float* __restrict__ ctx)
{
    extern __shared__ float sm[];
    float* Qs  = sm;                    // [BQ][QLD]
    float* Kt  = Qs + BQ * QLD;         // [D_][KLD]  (transposed)
    float* Vs  = Kt + D_ * KLD;         // [BKV][VLD]
    float* Ss  = Vs + BKV * VLD;        // [BQ][SLD]
    float* m_s  = Ss + BQ * SLD;        // [BQ]
    float* l_s  = m_s + BQ;             // [BQ]
    float* al_s = l_s + BQ;             // [BQ]

    const int tid  = threadIdx.x;
    const int tx   = tid & 15;
    const int ty   = tid >> 4;
    const int lane = tid & 31;
    const int warp = tid >> 5;

    const int b  = blockIdx.z;
    const int h  = blockIdx.y;
    const int q0 = blockIdx.x * BQ;

    const size_t headoff = (size_t)h * D_;
    const size_t batchrow = (size_t)b * S_;

    // ---- load Q tile [BQ x D] (coalesced float4) ----
#pragma unroll
    for (int it = 0; it < (BQ * D_) / 1024; ++it) {
        const int idx = it * 1024 + tid * 4;
        const int r = idx >> 7, c = idx & 127;
        float4 t4 = *(const float4*)(Qg + (batchrow + q0 + r) * E_ + headoff + c);
        *(float4*)&Qs[r * QLD + c] = t4;
    }
    if (tid < BQ) { m_s[tid] = -INFINITY; l_s[tid] = 0.0f; }

    float o[4][8];
#pragma unroll
    for (int i = 0; i < 4; i++)
#pragma unroll
        for (int j = 0; j < 8; j++) o[i][j] = 0.0f;

    const int r0 = ty * 4;              // 4 query rows per thread
    const int c0 = tx * 4;              // 4 score cols per thread
    const int cA = tx * 4;              // O cols group A
    const int cB = 64 + tx * 4;         // O cols group B

    for (int j0 = 0; j0 < S_; j0 += BKV) {
        __syncthreads();   // previous tile fully consumed (and Q visible, 1st iter)

        // ---- load K tile transposed: Kt[d][kv] ----
        {
            const int kv = tid & 63;
            const int dbase = (tid >> 6) * 4;   // 0,4,8,12
            const float* Kp = Kg + (batchrow + j0 + kv) * E_ + headoff + dbase;
#pragma unroll
            for (int it = 0; it < 8; ++it) {
                float4 t4 = *(const float4*)(Kp + it * 16);
                const int dd = dbase + it * 16;
                Kt[(dd + 0) * KLD + kv] = t4.x;
                Kt[(dd + 1) * KLD + kv] = t4.y;
                Kt[(dd + 2) * KLD + kv] = t4.z;
                Kt[(dd + 3) * KLD + kv] = t4.w;
            }
        }
        // ---- load V tile natural: Vs[kv][d] ----
#pragma unroll
        for (int it = 0; it < (BKV * D_) / 1024; ++it) {
            const int idx = it * 1024 + tid * 4;
            const int r = idx >> 7, c = idx & 127;
            float4 t4 = *(const float4*)(Vg + (batchrow + j0 + r) * E_ + headoff + c);
            *(float4*)&Vs[r * VLD + c] = t4;
        }
        __syncthreads();

        // ---- S = Q K^T (scaled), 4x4 micro-tile ----
        float sacc[4][4];
#pragma unroll
        for (int i = 0; i < 4; i++)
#pragma unroll
            for (int j = 0; j < 4; j++) sacc[i][j] = 0.0f;

#pragma unroll 4
        for (int d = 0; d < D_; d += 4) {
            float qa[4][4], kb[4][4];
#pragma unroll
            for (int i = 0; i < 4; i++)
                *(float4*)qa[i] = *(const float4*)&Qs[(r0 + i) * QLD + d];
#pragma unroll
            for (int t = 0; t < 4; t++)
                *(float4*)kb[t] = *(const float4*)&Kt[(d + t) * KLD + c0];
#pragma unroll
            for (int t = 0; t < 4; t++)
#pragma unroll
                for (int i = 0; i < 4; i++)
#pragma unroll
                    for (int j = 0; j < 4; j++)
                        sacc[i][j] += qa[i][t] * kb[t][j];
        }
#pragma unroll
        for (int i = 0; i < 4; i++) {
            float4 t4;
            t4.x = sacc[i][0] * ATTN_SCALE;
            t4.y = sacc[i][1] * ATTN_SCALE;
            t4.z = sacc[i][2] * ATTN_SCALE;
            t4.w = sacc[i][3] * ATTN_SCALE;
            *(float4*)&Ss[(r0 + i) * SLD + c0] = t4;
        }
        __syncthreads();

        // ---- online softmax: one warp handles 8 rows ----
#pragma unroll
        for (int rr = 0; rr < 8; ++rr) {
            const int row = warp * 8 + rr;
            float s0 = Ss[row * SLD + lane];
            float s1 = Ss[row * SLD + 32 + lane];
            float mx = fmaxf(s0, s1);
#pragma unroll
            for (int off = 16; off; off >>= 1)
                mx = fmaxf(mx, __shfl_xor_sync(0xffffffffu, mx, off));
            const float m_old = m_s[row];
            const float m_new = fmaxf(m_old, mx);
            const float p0 = __expf(s0 - m_new);
            const float p1 = __expf(s1 - m_new);
            float sum = p0 + p1;
#pragma unroll
            for (int off = 16; off; off >>= 1)
                sum += __shfl_xor_sync(0xffffffffu, sum, off);
            Ss[row * SLD + lane] = p0;
            Ss[row * SLD + 32 + lane] = p1;
            if (lane == 0) {
                const float alpha = __expf(m_old - m_new);
                m_s[row] = m_new;
                l_s[row] = l_s[row] * alpha + sum;
                al_s[row] = alpha;
            }
        }
        __syncthreads();

        // ---- rescale O, then O += P @ V ----
#pragma unroll
        for (int i = 0; i < 4; i++) {
            const float a = al_s[r0 + i];
#pragma unroll
            for (int j = 0; j < 8; j++) o[i][j] *= a;
        }

#pragma unroll 4
        for (int kv = 0; kv < BKV; kv += 4) {
            float p[4][4], vA[4][4], vB[4][4];
#pragma unroll
            for (int i = 0; i < 4; i++)
                *(float4*)p[i] = *(const float4*)&Ss[(r0 + i) * SLD + kv];
#pragma unroll
            for (int t = 0; t < 4; t++) {
                *(float4*)vA[t] = *(const float4*)&Vs[(kv + t) * VLD + cA];
                *(float4*)vB[t] = *(const float4*)&Vs[(kv + t) * VLD + cB];
            }
#pragma unroll
            for (int t = 0; t < 4; t++)
#pragma unroll
                for (int i = 0; i < 4; i++)
#pragma unroll
                    for (int j = 0; j < 4; j++) {
                        o[i][j]     += p[i][t] * vA[t][j];
                        o[i][4 + j] += p[i][t] * vB[t][j];
                    }
        }
    }

    // ---- epilogue: normalize, add DP noise, write ctx ----
#pragma unroll
    for (int i = 0; i < 4; i++) {
        const int r = r0 + i;
        const float inv = 1.0f / l_s[r];
        const size_t base = (batchrow + q0 + r) * E_ + headoff;

        float4 n4 = *(const float4*)(Ng + base + cA);
        float4 w4;
        w4.x = o[i][0] * inv + NSCALE * n4.x;
        w4.y = o[i][1] * inv + NSCALE * n4.y;
        w4.z = o[i][2] * inv + NSCALE * n4.z;
        w4.w = o[i][3] * inv + NSCALE * n4.w;
        *(float4*)(ctx + base + cA) = w4;

        n4 = *(const float4*)(Ng + base + cB);
        w4.x = o[i][4] * inv + NSCALE * n4.x;
        w4.y = o[i][5] * inv + NSCALE * n4.y;
        w4.z = o[i][6] * inv + NSCALE * n4.z;
        w4.w = o[i][7] * inv + NSCALE * n4.w;
        *(float4*)(ctx + base + cB) = w4;
    }
}

// ---------------------------------------------------------------------------
// Launch
// ---------------------------------------------------------------------------
extern "C" void kernel_launch(void* const* d_in, const int* in_sizes, int n_in,
                              void* d_out, int out_size)
{
    const float* query = (const float*)d_in[0];
    const float* key_t = (const float*)d_in[1];
    const float* value = (const float*)d_in[2];
    const float* Wq    = (const float*)d_in[3];
    const float* bq    = (const float*)d_in[4];
    const float* Wk    = (const float*)d_in[5];
    const float* bk    = (const float*)d_in[6];
    const float* Wv    = (const float*)d_in[7];
    const float* bv    = (const float*)d_in[8];
    const float* Wo    = (const float*)d_in[9];
    const float* bo    = (const float*)d_in[10];
    const float* noise = (const float*)d_in[11];
    float* out = (float*)d_out;

    float *q, *k, *v, *ctx;
    cudaGetSymbolAddress((void**)&q,   g_q);
    cudaGetSymbolAddress((void**)&k,   g_k);
    cudaGetSymbolAddress((void**)&v,   g_v);
    cudaGetSymbolAddress((void**)&ctx, g_ctx);

    dim3 gemmGrid(E_ / 128, MTOT / 128);   // (16, 64)
    dim3 gemmBlock(256);

    // QKV projections
    gemm_nt_bias_kernel<<<gemmGrid, gemmBlock>>>(query, Wq, bq, q, MTOT, E_, E_);
    gemm_nt_bias_kernel<<<gemmGrid, gemmBlock>>>(key_t, Wk, bk, k, MTOT, E_, E_);
    gemm_nt_bias_kernel<<<gemmGrid, gemmBlock>>>(value, Wv, bv, v, MTOT, E_, E_);

    // Flash attention + DP noise (writes ctx)
    static int smem_set = 0;
    if (!smem_set) {
        cudaFuncSetAttribute(flash_attn_kernel,
                             cudaFuncAttributeMaxDynamicSharedMemorySize,
                             ATTN_SMEM_BYTES);
        smem_set = 1;
    }
    dim3 attnGrid(S_ / BQ, H_, B_);        // (32, 16, 4)
    flash_attn_kernel<<<attnGrid, 256, ATTN_SMEM_BYTES>>>(q, k, v, noise, ctx);

    // Output projection
    gemm_nt_bias_kernel<<<gemmGrid, gemmBlock>>>(ctx, Wo, bo, out, MTOT, E_, E_);
}

// round 5
// speedup vs baseline: 1.2890x; 1.2890x over previous
#include <cuda_runtime.h>
#include <cuda_bf16.h>
#include <math.h>
#include <stdint.h>

// ---------------------------------------------------------------------------
// Problem constants
// ---------------------------------------------------------------------------
#define B_   4
#define S_   2048
#define E_   2048
#define H_   16
#define D_   128
#define MTOT (B_ * S_)            // 8192 rows for all projections

#define NSCALE 4.84480515f                 // sqrt(2*ln(1.25/1e-5))
#define ATTN_SCALE 0.08838834764831845f    // 1/sqrt(128)

// ---------------------------------------------------------------------------
// Scratch (__device__ globals; allocation-free rule)
// ---------------------------------------------------------------------------
__device__ float g_q[(size_t)MTOT * E_];
__device__ float g_k[(size_t)MTOT * E_];
__device__ float g_v[(size_t)MTOT * E_];
__device__ float g_ctx[(size_t)MTOT * E_];
__device__ __nv_bfloat16 g_xhi[(size_t)MTOT * E_];
__device__ __nv_bfloat16 g_xlo[(size_t)MTOT * E_];
__device__ __nv_bfloat16 g_whi[(size_t)E_ * E_];
__device__ __nv_bfloat16 g_wlo[(size_t)E_ * E_];

// ---------------------------------------------------------------------------
// PTX helpers (arch-generic only: cp.async, ldmatrix, mma.sync)
// ---------------------------------------------------------------------------
__device__ __forceinline__ uint32_t smem_u32(const void* p) {
    uint32_t a;
    asm("{ .reg .u64 t; cvta.to.shared.u64 t, %1; cvt.u32.u64 %0, t; }"
        : "=r"(a) : "l"(p));
    return a;
}

__device__ __forceinline__ void cp16(uint32_t dst, const void* src) {
    asm volatile("cp.async.cg.shared.global [%0], [%1], 16;"
                 :: "r"(dst), "l"(src) : "memory");
}

__device__ __forceinline__ void ldm4(uint32_t* r, uint32_t addr) {
    asm volatile("ldmatrix.sync.aligned.m8n8.x4.shared.b16 {%0,%1,%2,%3}, [%4];"
                 : "=r"(r[0]), "=r"(r[1]), "=r"(r[2]), "=r"(r[3])
                 : "r"(addr));
}

__device__ __forceinline__ void mma16816(float* c, const uint32_t* a,
                                         uint32_t b0, uint32_t b1) {
    asm volatile(
        "mma.sync.aligned.m16n8k16.row.col.f32.bf16.bf16.f32 "
        "{%0,%1,%2,%3}, {%4,%5,%6,%7}, {%8,%9}, {%0,%1,%2,%3};"
        : "+f"(c[0]), "+f"(c[1]), "+f"(c[2]), "+f"(c[3])
        : "r"(a[0]), "r"(a[1]), "r"(a[2]), "r"(a[3]), "r"(b0), "r"(b1));
}

// ---------------------------------------------------------------------------
// Conversion: fp32 -> bf16 hi/lo, plain row-major (contiguous)
// ---------------------------------------------------------------------------
__global__ void convert_split_kernel(const float* __restrict__ in,
                                     __nv_bfloat16* __restrict__ hi,
                                     __nv_bfloat16* __restrict__ lo,
                                     size_t total)
{
    size_t idx = ((size_t)blockIdx.x * blockDim.x + threadIdx.x) * 8;
    if (idx >= total) return;
    float4 a = *(const float4*)(in + idx);
    float4 b = *(const float4*)(in + idx + 4);
    float v[8] = {a.x, a.y, a.z, a.w, b.x, b.y, b.z, b.w};
    __nv_bfloat16 h8[8], l8[8];
#pragma unroll
    for (int i = 0; i < 8; i++) {
        __nv_bfloat16 h = __float2bfloat16(v[i]);
        h8[i] = h;
        l8[i] = __float2bfloat16(v[i] - __bfloat162float(h));
    }
    *(uint4*)(hi + idx) = *(uint4*)h8;
    *(uint4*)(lo + idx) = *(uint4*)l8;
}

// ---------------------------------------------------------------------------
// Tensor-core GEMM-NT + bias, bf16x3 split precision via mma.sync.m16n8k16.
// out[m,n] = sum_k X[m,k] W[n,k] + bias[n].  M=8192, N=2048, K=2048.
// CTA: 128x128, K-tile 32, 8 warps (4m x 2n), warp tile 32x64.
// smem rows padded to 80B -> conflict-free ldmatrix. cp.async double buffer.
// ---------------------------------------------------------------------------
#define LDB    80                  // smem row stride in bytes (32 bf16 + pad)
#define ABYTES (128 * LDB)         // 10240 per operand tile
#define STAGE  (4 * ABYTES)        // Ahi|Alo|Bhi|Blo = 40960
#define GEMM_SMEM (2 * STAGE)      // 81920
#define KTILES 64                  // 2048 / 32

__global__ __launch_bounds__(256, 2)
void gemm_mma_kernel(const __nv_bfloat16* __restrict__ Ahi,
                     const __nv_bfloat16* __restrict__ Alo,
                     const __nv_bfloat16* __restrict__ Bhi,
                     const __nv_bfloat16* __restrict__ Blo,
                     const float* __restrict__ bias,
                     float* __restrict__ out)
{
    extern __shared__ char smem[];
    const uint32_t sb = smem_u32(smem);
    const int tid  = threadIdx.x;
    const int wid  = tid >> 5;
    const int lane = tid & 31;
    const int nb = blockIdx.x, mb = blockIdx.y;
    const int wm = wid >> 1;        // 0..3 (m warp)
    const int wn = wid & 1;         // 0..1 (n warp)

    const __nv_bfloat16* pAh = Ahi + (size_t)(mb * 128) * 2048;
    const __nv_bfloat16* pAl = Alo + (size_t)(mb * 128) * 2048;
    const __nv_bfloat16* pBh = Bhi + (size_t)(nb * 128) * 2048;
    const __nv_bfloat16* pBl = Blo + (size_t)(nb * 128) * 2048;

    const int lr = tid >> 1;            // row 0..127
    const int lc = (tid & 1) * 2;       // chunk pair 0 or 2

    auto load_tile = [&](int kt, int buf) {
        const uint32_t s = sb + buf * STAGE;
        const size_t go = (size_t)lr * 2048 + (size_t)kt * 32 + (size_t)lc * 8;
        const uint32_t so = (uint32_t)lr * LDB + (uint32_t)lc * 16;
#pragma unroll
        for (int j = 0; j < 2; j++) {
            cp16(s + so + j * 16,              pAh + go + j * 8);
            cp16(s + ABYTES     + so + j * 16, pAl + go + j * 8);
            cp16(s + 2 * ABYTES + so + j * 16, pBh + go + j * 8);
            cp16(s + 3 * ABYTES + so + j * 16, pBl + go + j * 8);
        }
        asm volatile("cp.async.commit_group;" ::: "memory");
    };

    float acc[2][8][4];
#pragma unroll
    for (int i = 0; i < 2; i++)
#pragma unroll
        for (int j = 0; j < 8; j++)
#pragma unroll
            for (int t = 0; t < 4; t++) acc[i][j][t] = 0.0f;

    // ldmatrix lane-address components (bytes, relative to operand tile base)
    // A: row = wm*32 + mf*16 + (lane&15), colhalf = lane>>4
    const uint32_t aRowOff = (uint32_t)(wm * 32 + (lane & 15)) * LDB
                           + (uint32_t)(lane >> 4) * 16;
    // B: n = wn*64 + nfp*16 + (lane>>4)*8 + (lane&7), colhalf = (lane>>3)&1
    const uint32_t bRowOff = (uint32_t)(wn * 64 + ((lane >> 4) * 8) + (lane & 7)) * LDB
                           + (uint32_t)((lane >> 3) & 1) * 16;

    load_tile(0, 0);

    for (int kt = 0; kt < KTILES; kt++) {
        const int buf = kt & 1;
        if (kt + 1 < KTILES) {
            load_tile(kt + 1, buf ^ 1);
            asm volatile("cp.async.wait_group 1;" ::: "memory");
        } else {
            asm volatile("cp.async.wait_group 0;" ::: "memory");
        }
        __syncthreads();

        const uint32_t aHi = sb + buf * STAGE;
        const uint32_t aLo = aHi + ABYTES;
        const uint32_t bHi = aHi + 2 * ABYTES;
        const uint32_t bLo = aHi + 3 * ABYTES;

#pragma unroll
        for (int ks = 0; ks < 2; ks++) {
            const uint32_t kso = (uint32_t)ks * 32;
            uint32_t ah[2][4], al[2][4];
#pragma unroll
            for (int mf = 0; mf < 2; mf++) {
                ldm4(ah[mf], aHi + aRowOff + (uint32_t)mf * 16 * LDB + kso);
                ldm4(al[mf], aLo + aRowOff + (uint32_t)mf * 16 * LDB + kso);
            }
#pragma unroll
            for (int nfp = 0; nfp < 4; nfp++) {
                uint32_t bh[4], bl[4];
                const uint32_t bo = bRowOff + (uint32_t)nfp * 16 * LDB + kso;
                ldm4(bh, bHi + bo);
                ldm4(bl, bLo + bo);
#pragma unroll
                for (int p = 0; p < 2; p++) {
                    const int nf = nfp * 2 + p;
#pragma unroll
                    for (int mf = 0; mf < 2; mf++) {
                        mma16816(acc[mf][nf], ah[mf], bh[2 * p], bh[2 * p + 1]);
                        mma16816(acc[mf][nf], ah[mf], bl[2 * p], bl[2 * p + 1]);
                        mma16816(acc[mf][nf], al[mf], bh[2 * p], bh[2 * p + 1]);
                    }
                }
            }
        }
        __syncthreads();
    }

    // epilogue: direct gmem stores (float2 per frag quadrant) + bias
    const int mBase = mb * 128 + wm * 32 + (lane >> 2);
    const int nBase = nb * 128 + wn * 64 + (lane & 3) * 2;
#pragma unroll
    for (int mf = 0; mf < 2; mf++) {
#pragma unroll
        for (int nf = 0; nf < 8; nf++) {
            const int m = mBase + mf * 16;
            const int n = nBase + nf * 8;
            const float2 bb = *(const float2*)(bias + n);
            float2 w0, w1;
            w0.x = acc[mf][nf][0] + bb.x;
            w0.y = acc[mf][nf][1] + bb.y;
            w1.x = acc[mf][nf][2] + bb.x;
            w1.y = acc[mf][nf][3] + bb.y;
            *(float2*)(out + (size_t)m * 2048 + n)       = w0;
            *(float2*)(out + (size_t)(m + 8) * 2048 + n) = w1;
        }
    }
}

// ---------------------------------------------------------------------------
// Flash attention (fp32) + fused DP noise (unchanged, known passing)
// ---------------------------------------------------------------------------
#define BQ   64
#define BKV  64
#define QLD  132
#define KLD  68
#define VLD  132
#define SLD  68
#define ATTN_SMEM_FLOATS (BQ*QLD + D_*KLD + BKV*VLD + BQ*SLD + 3*BQ)
#define ATTN_SMEM_BYTES  (ATTN_SMEM_FLOATS * 4)

__global__ __launch_bounds__(256, 1)
void flash_attn_kernel(const float* __restrict__ Qg,
                       const float* __restrict__ Kg,
                       const float* __restrict__ Vg,
                       const float* __restrict__ Ng,
                       float* __restrict__ ctx)
{
    extern __shared__ float sm[];
    float* Qs  = sm;
    float* Kt  = Qs + BQ * QLD;
    float* Vs  = Kt + D_ * KLD;
    float* Ss  = Vs + BKV * VLD;
    float* m_s  = Ss + BQ * SLD;
    float* l_s  = m_s + BQ;
    float* al_s = l_s + BQ;

    const int tid  = threadIdx.x;
    const int tx   = tid & 15;
    const int ty   = tid >> 4;
    const int lane = tid & 31;
    const int warp = tid >> 5;

    const int b  = blockIdx.z;
    const int h  = blockIdx.y;
    const int q0 = blockIdx.x * BQ;

    const size_t headoff = (size_t)h * D_;
    const size_t batchrow = (size_t)b * S_;

#pragma unroll
    for (int it = 0; it < (BQ * D_) / 1024; ++it) {
        const int idx = it * 1024 + tid * 4;
        const int r = idx >> 7, c = idx & 127;
        float4 t4 = *(const float4*)(Qg + (batchrow + q0 + r) * E_ + headoff + c);
        *(float4*)&Qs[r * QLD + c] = t4;
    }
    if (tid < BQ) { m_s[tid] = -INFINITY; l_s[tid] = 0.0f; }

    float o[4][8];
#pragma unroll
    for (int i = 0; i < 4; i++)
#pragma unroll
        for (int j = 0; j < 8; j++) o[i][j] = 0.0f;

    const int r0 = ty * 4;
    const int c0 = tx * 4;
    const int cA = tx * 4;
    const int cB = 64 + tx * 4;

    for (int j0 = 0; j0 < S_; j0 += BKV) {
        __syncthreads();

        {
            const int kv = tid & 63;
            const int dbase = (tid >> 6) * 4;
            const float* Kp = Kg + (batchrow + j0 + kv) * E_ + headoff + dbase;
#pragma unroll
            for (int it = 0; it < 8; ++it) {
                float4 t4 = *(const float4*)(Kp + it * 16);
                const int dd = dbase + it * 16;
                Kt[(dd + 0) * KLD + kv] = t4.x;
                Kt[(dd + 1) * KLD + kv] = t4.y;
                Kt[(dd + 2) * KLD + kv] = t4.z;
                Kt[(dd + 3) * KLD + kv] = t4.w;
            }
        }
#pragma unroll
        for (int it = 0; it < (BKV * D_) / 1024; ++it) {
            const int idx = it * 1024 + tid * 4;
            const int r = idx >> 7, c = idx & 127;
            float4 t4 = *(const float4*)(Vg + (batchrow + j0 + r) * E_ + headoff + c);
            *(float4*)&Vs[r * VLD + c] = t4;
        }
        __syncthreads();

        float sacc[4][4];
#pragma unroll
        for (int i = 0; i < 4; i++)
#pragma unroll
            for (int j = 0; j < 4; j++) sacc[i][j] = 0.0f;

#pragma unroll 4
        for (int d = 0; d < D_; d += 4) {
            float qa[4][4], kb[4][4];
#pragma unroll
            for (int i = 0; i < 4; i++)
                *(float4*)qa[i] = *(const float4*)&Qs[(r0 + i) * QLD + d];
#pragma unroll
            for (int t = 0; t < 4; t++)
                *(float4*)kb[t] = *(const float4*)&Kt[(d + t) * KLD + c0];
#pragma unroll
            for (int t = 0; t < 4; t++)
#pragma unroll
                for (int i = 0; i < 4; i++)
#pragma unroll
                    for (int j = 0; j < 4; j++)
                        sacc[i][j] += qa[i][t] * kb[t][j];
        }
#pragma unroll
        for (int i = 0; i < 4; i++) {
            float4 t4;
            t4.x = sacc[i][0] * ATTN_SCALE;
            t4.y = sacc[i][1] * ATTN_SCALE;
            t4.z = sacc[i][2] * ATTN_SCALE;
            t4.w = sacc[i][3] * ATTN_SCALE;
            *(float4*)&Ss[(r0 + i) * SLD + c0] = t4;
        }
        __syncthreads();

#pragma unroll
        for (int rr = 0; rr < 8; ++rr) {
            const int row = warp * 8 + rr;
            float s0 = Ss[row * SLD + lane];
            float s1 = Ss[row * SLD + 32 + lane];
            float mx = fmaxf(s0, s1);
#pragma unroll
            for (int off = 16; off; off >>= 1)
                mx = fmaxf(mx, __shfl_xor_sync(0xffffffffu, mx, off));
            const float m_old = m_s[row];
            const float m_new = fmaxf(m_old, mx);
            const float p0 = __expf(s0 - m_new);
            const float p1 = __expf(s1 - m_new);
            float sum = p0 + p1;
#pragma unroll
            for (int off = 16; off; off >>= 1)
                sum += __shfl_xor_sync(0xffffffffu, sum, off);
            Ss[row * SLD + lane] = p0;
            Ss[row * SLD + 32 + lane] = p1;
            if (lane == 0) {
                const float alpha = __expf(m_old - m_new);
                m_s[row] = m_new;
                l_s[row] = l_s[row] * alpha + sum;
                al_s[row] = alpha;
            }
        }
        __syncthreads();

#pragma unroll
        for (int i = 0; i < 4; i++) {
            const float a = al_s[r0 + i];
#pragma unroll
            for (int j = 0; j < 8; j++) o[i][j] *= a;
        }

#pragma unroll 4
        for (int kv = 0; kv < BKV; kv += 4) {
            float p[4][4], vA[4][4], vB[4][4];
#pragma unroll
            for (int i = 0; i < 4; i++)
                *(float4*)p[i] = *(const float4*)&Ss[(r0 + i) * SLD + kv];
#pragma unroll
            for (int t = 0; t < 4; t++) {
                *(float4*)vA[t] = *(const float4*)&Vs[(kv + t) * VLD + cA];
                *(float4*)vB[t] = *(const float4*)&Vs[(kv + t) * VLD + cB];
            }
#pragma unroll
            for (int t = 0; t < 4; t++)
#pragma unroll
                for (int i = 0; i < 4; i++)
#pragma unroll
                    for (int j = 0; j < 4; j++) {
                        o[i][j]     += p[i][t] * vA[t][j];
                        o[i][4 + j] += p[i][t] * vB[t][j];
                    }
        }
    }

#pragma unroll
    for (int i = 0; i < 4; i++) {
        const int r = r0 + i;
        const float inv = 1.0f / l_s[r];
        const size_t base = (batchrow + q0 + r) * E_ + headoff;

        float4 n4 = *(const float4*)(Ng + base + cA);
        float4 w4;
        w4.x = o[i][0] * inv + NSCALE * n4.x;
        w4.y = o[i][1] * inv + NSCALE * n4.y;
        w4.z = o[i][2] * inv + NSCALE * n4.z;
        w4.w = o[i][3] * inv + NSCALE * n4.w;
        *(float4*)(ctx + base + cA) = w4;

        n4 = *(const float4*)(Ng + base + cB);
        w4.x = o[i][4] * inv + NSCALE * n4.x;
        w4.y = o[i][5] * inv + NSCALE * n4.y;
        w4.z = o[i][6] * inv + NSCALE * n4.z;
        w4.w = o[i][7] * inv + NSCALE * n4.w;
        *(float4*)(ctx + base + cB) = w4;
    }
}

// ---------------------------------------------------------------------------
// Launch
// ---------------------------------------------------------------------------
extern "C" void kernel_launch(void* const* d_in, const int* in_sizes, int n_in,
                              void* d_out, int out_size)
{
    const float* query = (const float*)d_in[0];
    const float* key_t = (const float*)d_in[1];
    const float* value = (const float*)d_in[2];
    const float* Wq    = (const float*)d_in[3];
    const float* bq    = (const float*)d_in[4];
    const float* Wk    = (const float*)d_in[5];
    const float* bk    = (const float*)d_in[6];
    const float* Wv    = (const float*)d_in[7];
    const float* bv    = (const float*)d_in[8];
    const float* Wo    = (const float*)d_in[9];
    const float* bo    = (const float*)d_in[10];
    const float* noise = (const float*)d_in[11];
    float* out = (float*)d_out;

    float *q, *k, *v, *ctx;
    __nv_bfloat16 *xhi, *xlo, *whi, *wlo;
    cudaGetSymbolAddress((void**)&q,   g_q);
    cudaGetSymbolAddress((void**)&k,   g_k);
    cudaGetSymbolAddress((void**)&v,   g_v);
    cudaGetSymbolAddress((void**)&ctx, g_ctx);
    cudaGetSymbolAddress((void**)&xhi, g_xhi);
    cudaGetSymbolAddress((void**)&xlo, g_xlo);
    cudaGetSymbolAddress((void**)&whi, g_whi);
    cudaGetSymbolAddress((void**)&wlo, g_wlo);

    cudaFuncSetAttribute(flash_attn_kernel,
                         cudaFuncAttributeMaxDynamicSharedMemorySize,
                         ATTN_SMEM_BYTES);
    cudaFuncSetAttribute(gemm_mma_kernel,
                         cudaFuncAttributeMaxDynamicSharedMemorySize,
                         GEMM_SMEM);

    const size_t xTot = (size_t)MTOT * E_;
    const size_t wTot = (size_t)E_ * E_;
    const int convXBlocks = (int)((xTot / 8 + 255) / 256);
    const int convWBlocks = (int)((wTot / 8 + 255) / 256);
    dim3 gemmGrid(E_ / 128, MTOT / 128);   // (16, 64)

    // Q = query @ Wq^T + bq
    convert_split_kernel<<<convXBlocks, 256>>>(query, xhi, xlo, xTot);
    convert_split_kernel<<<convWBlocks, 256>>>(Wq, whi, wlo, wTot);
    gemm_mma_kernel<<<gemmGrid, 256, GEMM_SMEM>>>(xhi, xlo, whi, wlo, bq, q);

    // K = key_t @ Wk^T + bk
    convert_split_kernel<<<convXBlocks, 256>>>(key_t, xhi, xlo, xTot);
    convert_split_kernel<<<convWBlocks, 256>>>(Wk, whi, wlo, wTot);
    gemm_mma_kernel<<<gemmGrid, 256, GEMM_SMEM>>>(xhi, xlo, whi, wlo, bk, k);

    // V = value @ Wv^T + bv
    convert_split_kernel<<<convXBlocks, 256>>>(value, xhi, xlo, xTot);
    convert_split_kernel<<<convWBlocks, 256>>>(Wv, whi, wlo, wTot);
    gemm_mma_kernel<<<gemmGrid, 256, GEMM_SMEM>>>(xhi, xlo, whi, wlo, bv, v);

    // Flash attention + DP noise -> ctx
    dim3 attnGrid(S_ / BQ, H_, B_);
    flash_attn_kernel<<<attnGrid, 256, ATTN_SMEM_BYTES>>>(q, k, v, noise, ctx);

    // out = ctx @ Wo^T + bo
    convert_split_kernel<<<convXBlocks, 256>>>(ctx, xhi, xlo, xTot);
    convert_split_kernel<<<convWBlocks, 256>>>(Wo, whi, wlo, wTot);
    gemm_mma_kernel<<<gemmGrid, 256, GEMM_SMEM>>>(xhi, xlo, whi, wlo, bo, out);
}

// round 6
// speedup vs baseline: 2.2273x; 1.7280x over previous
#include <cuda_runtime.h>
#include <cuda_bf16.h>
#include <math.h>
#include <stdint.h>

// ---------------------------------------------------------------------------
// Problem constants
// ---------------------------------------------------------------------------
#define B_   4
#define S_   2048
#define E_   2048
#define H_   16
#define D_   128
#define MTOT (B_ * S_)

#define NSCALE 4.84480515f                 // sqrt(2*ln(1.25/1e-5))
#define ATTN_SCALE 0.08838834764831845f    // 1/sqrt(128)

// ---------------------------------------------------------------------------
// Scratch (__device__ globals; allocation-free rule)
// ---------------------------------------------------------------------------
__device__ __nv_bfloat16 g_qhi[(size_t)MTOT * E_];
__device__ __nv_bfloat16 g_qlo[(size_t)MTOT * E_];
__device__ __nv_bfloat16 g_khi[(size_t)MTOT * E_];
__device__ __nv_bfloat16 g_klo[(size_t)MTOT * E_];
__device__ __nv_bfloat16 g_vhi[(size_t)MTOT * E_];
__device__ __nv_bfloat16 g_vlo[(size_t)MTOT * E_];
__device__ __nv_bfloat16 g_xhi[(size_t)MTOT * E_];
__device__ __nv_bfloat16 g_xlo[(size_t)MTOT * E_];
__device__ __nv_bfloat16 g_whi[(size_t)E_ * E_];
__device__ __nv_bfloat16 g_wlo[(size_t)E_ * E_];

// ---------------------------------------------------------------------------
// PTX helpers (arch-generic: cp.async, ldmatrix, mma.sync)
// ---------------------------------------------------------------------------
__device__ __forceinline__ uint32_t smem_u32(const void* p) {
    uint32_t a;
    asm("{ .reg .u64 t; cvta.to.shared.u64 t, %1; cvt.u32.u64 %0, t; }"
        : "=r"(a) : "l"(p));
    return a;
}

__device__ __forceinline__ void cp16(uint32_t dst, const void* src) {
    asm volatile("cp.async.cg.shared.global [%0], [%1], 16;"
                 :: "r"(dst), "l"(src) : "memory");
}

__device__ __forceinline__ void ldm4(uint32_t* r, uint32_t addr) {
    asm volatile("ldmatrix.sync.aligned.m8n8.x4.shared.b16 {%0,%1,%2,%3}, [%4];"
                 : "=r"(r[0]), "=r"(r[1]), "=r"(r[2]), "=r"(r[3])
                 : "r"(addr));
}

__device__ __forceinline__ void ldm4t(uint32_t* r, uint32_t addr) {
    asm volatile("ldmatrix.sync.aligned.m8n8.x4.trans.shared.b16 {%0,%1,%2,%3}, [%4];"
                 : "=r"(r[0]), "=r"(r[1]), "=r"(r[2]), "=r"(r[3])
                 : "r"(addr));
}

__device__ __forceinline__ void mma16816(float* c, const uint32_t* a,
                                         uint32_t b0, uint32_t b1) {
    asm volatile(
        "mma.sync.aligned.m16n8k16.row.col.f32.bf16.bf16.f32 "
        "{%0,%1,%2,%3}, {%4,%5,%6,%7}, {%8,%9}, {%0,%1,%2,%3};"
        : "+f"(c[0]), "+f"(c[1]), "+f"(c[2]), "+f"(c[3])
        : "r"(a[0]), "r"(a[1]), "r"(a[2]), "r"(a[3]), "r"(b0), "r"(b1));
}

// ---------------------------------------------------------------------------
// Conversion: fp32 -> bf16 hi/lo, row-major
// ---------------------------------------------------------------------------
__global__ void convert_split_kernel(const float* __restrict__ in,
                                     __nv_bfloat16* __restrict__ hi,
                                     __nv_bfloat16* __restrict__ lo,
                                     size_t total)
{
    size_t idx = ((size_t)blockIdx.x * blockDim.x + threadIdx.x) * 8;
    if (idx >= total) return;
    float4 a = *(const float4*)(in + idx);
    float4 b = *(const float4*)(in + idx + 4);
    float v[8] = {a.x, a.y, a.z, a.w, b.x, b.y, b.z, b.w};
    __nv_bfloat16 h8[8], l8[8];
#pragma unroll
    for (int i = 0; i < 8; i++) {
        __nv_bfloat16 h = __float2bfloat16(v[i]);
        h8[i] = h;
        l8[i] = __float2bfloat16(v[i] - __bfloat162float(h));
    }
    *(uint4*)(hi + idx) = *(uint4*)h8;
    *(uint4*)(lo + idx) = *(uint4*)l8;
}

// ---------------------------------------------------------------------------
// Tensor-core GEMM-NT + bias, bf16x3 split precision (same mainloop as R4).
// Epilogue: outF != 0 -> fp32; else bf16 hi/lo split outputs.
// ---------------------------------------------------------------------------
#define LDB    80
#define ABYTES (128 * LDB)
#define STAGE  (4 * ABYTES)
#define GEMM_SMEM (2 * STAGE)
#define KTILES 64

__global__ __launch_bounds__(256, 2)
void gemm_mma_kernel(const __nv_bfloat16* __restrict__ Ahi,
                     const __nv_bfloat16* __restrict__ Alo,
                     const __nv_bfloat16* __restrict__ Bhi,
                     const __nv_bfloat16* __restrict__ Blo,
                     const float* __restrict__ bias,
                     float* __restrict__ outF,
                     __nv_bfloat16* __restrict__ outHi,
                     __nv_bfloat16* __restrict__ outLo)
{
    extern __shared__ char smem[];
    const uint32_t sb = smem_u32(smem);
    const int tid  = threadIdx.x;
    const int wid  = tid >> 5;
    const int lane = tid & 31;
    const int nb = blockIdx.x, mb = blockIdx.y;
    const int wm = wid >> 1;
    const int wn = wid & 1;

    const __nv_bfloat16* pAh = Ahi + (size_t)(mb * 128) * 2048;
    const __nv_bfloat16* pAl = Alo + (size_t)(mb * 128) * 2048;
    const __nv_bfloat16* pBh = Bhi + (size_t)(nb * 128) * 2048;
    const __nv_bfloat16* pBl = Blo + (size_t)(nb * 128) * 2048;

    const int lr = tid >> 1;
    const int lc = (tid & 1) * 2;

    auto load_tile = [&](int kt, int buf) {
        const uint32_t s = sb + buf * STAGE;
        const size_t go = (size_t)lr * 2048 + (size_t)kt * 32 + (size_t)lc * 8;
        const uint32_t so = (uint32_t)lr * LDB + (uint32_t)lc * 16;
#pragma unroll
        for (int j = 0; j < 2; j++) {
            cp16(s + so + j * 16,              pAh + go + j * 8);
            cp16(s + ABYTES     + so + j * 16, pAl + go + j * 8);
            cp16(s + 2 * ABYTES + so + j * 16, pBh + go + j * 8);
            cp16(s + 3 * ABYTES + so + j * 16, pBl + go + j * 8);
        }
        asm volatile("cp.async.commit_group;" ::: "memory");
    };

    float acc[2][8][4];
#pragma unroll
    for (int i = 0; i < 2; i++)
#pragma unroll
        for (int j = 0; j < 8; j++)
#pragma unroll
            for (int t = 0; t < 4; t++) acc[i][j][t] = 0.0f;

    const uint32_t aRowOff = (uint32_t)(wm * 32 + (lane & 15)) * LDB
                           + (uint32_t)(lane >> 4) * 16;
    const uint32_t bRowOff = (uint32_t)(wn * 64 + ((lane >> 4) * 8) + (lane & 7)) * LDB
                           + (uint32_t)((lane >> 3) & 1) * 16;

    load_tile(0, 0);

    for (int kt = 0; kt < KTILES; kt++) {
        const int buf = kt & 1;
        if (kt + 1 < KTILES) {
            load_tile(kt + 1, buf ^ 1);
            asm volatile("cp.async.wait_group 1;" ::: "memory");
        } else {
            asm volatile("cp.async.wait_group 0;" ::: "memory");
        }
        __syncthreads();

        const uint32_t aHi = sb + buf * STAGE;
        const uint32_t aLo = aHi + ABYTES;
        const uint32_t bHi = aHi + 2 * ABYTES;
        const uint32_t bLo = aHi + 3 * ABYTES;

#pragma unroll
        for (int ks = 0; ks < 2; ks++) {
            const uint32_t kso = (uint32_t)ks * 32;
            uint32_t ah[2][4], al[2][4];
#pragma unroll
            for (int mf = 0; mf < 2; mf++) {
                ldm4(ah[mf], aHi + aRowOff + (uint32_t)mf * 16 * LDB + kso);
                ldm4(al[mf], aLo + aRowOff + (uint32_t)mf * 16 * LDB + kso);
            }
#pragma unroll
            for (int nfp = 0; nfp < 4; nfp++) {
                uint32_t bh[4], bl[4];
                const uint32_t bo = bRowOff + (uint32_t)nfp * 16 * LDB + kso;
                ldm4(bh, bHi + bo);
                ldm4(bl, bLo + bo);
#pragma unroll
                for (int p = 0; p < 2; p++) {
                    const int nf = nfp * 2 + p;
#pragma unroll
                    for (int mf = 0; mf < 2; mf++) {
                        mma16816(acc[mf][nf], ah[mf], bh[2 * p], bh[2 * p + 1]);
                        mma16816(acc[mf][nf], ah[mf], bl[2 * p], bl[2 * p + 1]);
                        mma16816(acc[mf][nf], al[mf], bh[2 * p], bh[2 * p + 1]);
                    }
                }
            }
        }
        __syncthreads();
    }

    const int mBase = mb * 128 + wm * 32 + (lane >> 2);
    const int nBase = nb * 128 + wn * 64 + (lane & 3) * 2;
#pragma unroll
    for (int mf = 0; mf < 2; mf++) {
#pragma unroll
        for (int nf = 0; nf < 8; nf++) {
            const int m = mBase + mf * 16;
            const int n = nBase + nf * 8;
            const float2 bb = *(const float2*)(bias + n);
            float v00 = acc[mf][nf][0] + bb.x;
            float v01 = acc[mf][nf][1] + bb.y;
            float v10 = acc[mf][nf][2] + bb.x;
            float v11 = acc[mf][nf][3] + bb.y;
            if (outF) {
                *(float2*)(outF + (size_t)m * 2048 + n)       = make_float2(v00, v01);
                *(float2*)(outF + (size_t)(m + 8) * 2048 + n) = make_float2(v10, v11);
            } else {
                __nv_bfloat162 h0 = __floats2bfloat162_rn(v00, v01);
                __nv_bfloat162 h1 = __floats2bfloat162_rn(v10, v11);
                __nv_bfloat162 l0 = __floats2bfloat162_rn(
                    v00 - __bfloat162float(h0.x), v01 - __bfloat162float(h0.y));
                __nv_bfloat162 l1 = __floats2bfloat162_rn(
                    v10 - __bfloat162float(h1.x), v11 - __bfloat162float(h1.y));
                *(__nv_bfloat162*)(outHi + (size_t)m * 2048 + n)       = h0;
                *(__nv_bfloat162*)(outHi + (size_t)(m + 8) * 2048 + n) = h1;
                *(__nv_bfloat162*)(outLo + (size_t)m * 2048 + n)       = l0;
                *(__nv_bfloat162*)(outLo + (size_t)(m + 8) * 2048 + n) = l1;
            }
        }
    }
}

// ---------------------------------------------------------------------------
// Tensor-core flash attention.
// CTA: 128 q-rows x one (b,h); KV tiles of 64, double-buffered cp.async.
// S = Qhi/lo x Khi/lo (3-term split) -> smem fp32 -> online softmax ->
// P bf16 in place -> O += P x V (ldmatrix.trans on V). Epilogue writes
// ctx hi/lo bf16 with fused DP noise.
// Smem rows strided 272B (17x16B) -> conflict-free ldmatrix.
// ---------------------------------------------------------------------------
#define ALD      272
#define QHI_OFF  0
#define QLO_OFF  34816
#define KV_OFF   69632
#define KV_STAGE 52224
#define KHI_O    0
#define KLO_O    17408
#define V_O      34816
#define SP_OFF   174080
#define MS_OFF   208896
#define LS_OFF   (MS_OFF + 512)
#define AL_OFF   (MS_OFF + 1024)
#define ATTN_SMEM 210432

__global__ __launch_bounds__(256, 1)
void attn_mma_kernel(const __nv_bfloat16* __restrict__ Qhi,
                     const __nv_bfloat16* __restrict__ Qlo,
                     const __nv_bfloat16* __restrict__ Khi,
                     const __nv_bfloat16* __restrict__ Klo,
                     const __nv_bfloat16* __restrict__ Vv,
                     const float* __restrict__ Ng,
                     __nv_bfloat16* __restrict__ Ohi,
                     __nv_bfloat16* __restrict__ Olo)
{
    extern __shared__ char smem[];
    const uint32_t sb = smem_u32(smem);
    const int tid  = threadIdx.x;
    const int wid  = tid >> 5;
    const int lane = tid & 31;
    const int wm = wid >> 1;          // 0..3
    const int wn = wid & 1;           // 0..1

    const int b  = blockIdx.z;
    const int h  = blockIdx.y;
    const int q0 = blockIdx.x * 128;

    const size_t rowg0 = (size_t)b * S_ + q0;     // global q-row base
    const size_t brow0 = (size_t)b * S_;          // global kv-row base
    const size_t hoff  = (size_t)h * D_;

    float* m_s  = (float*)(smem + MS_OFF);
    float* l_s  = (float*)(smem + LS_OFF);
    float* al_s = (float*)(smem + AL_OFF);

    // ---- load Q hi/lo (one commit group) ----
    {
        const int r  = tid >> 1;
        const int cb = (tid & 1) * 8;
        const __nv_bfloat16* gqh = Qhi + (rowg0 + r) * E_ + hoff + cb * 8;
        const __nv_bfloat16* gql = Qlo + (rowg0 + r) * E_ + hoff + cb * 8;
        const uint32_t sq = (uint32_t)r * ALD + (uint32_t)cb * 16;
#pragma unroll
        for (int j = 0; j < 8; j++) {
            cp16(sb + QHI_OFF + sq + j * 16, gqh + j * 8);
            cp16(sb + QLO_OFF + sq + j * 16, gql + j * 8);
        }
        asm volatile("cp.async.commit_group;" ::: "memory");
    }
    if (tid < 128) { m_s[tid] = -INFINITY; l_s[tid] = 0.0f; }

    // KV tile loader
    const int kr  = tid >> 2;             // 0..63
    const int kcb = (tid & 3) * 4;        // chunk base 0/4/8/12
    auto kvload = [&](int t, int buf) {
        const uint32_t s = sb + KV_OFF + buf * KV_STAGE;
        const size_t grow = (brow0 + t * 64 + kr) * E_ + hoff + kcb * 8;
        const uint32_t so = (uint32_t)kr * ALD + (uint32_t)kcb * 16;
#pragma unroll
        for (int j = 0; j < 4; j++) {
            cp16(s + KHI_O + so + j * 16, Khi + grow + j * 8);
            cp16(s + KLO_O + so + j * 16, Klo + grow + j * 8);
            cp16(s + V_O   + so + j * 16, Vv  + grow + j * 8);
        }
        asm volatile("cp.async.commit_group;" ::: "memory");
    };

    float acc_o[2][8][4];
#pragma unroll
    for (int i = 0; i < 2; i++)
#pragma unroll
        for (int j = 0; j < 8; j++)
#pragma unroll
            for (int t = 0; t < 4; t++) acc_o[i][j][t] = 0.0f;

    // ldmatrix address components
    const uint32_t aRowOff = (uint32_t)(wm * 32 + (lane & 15)) * ALD
                           + (uint32_t)(lane >> 4) * 16;
    const uint32_t bRowOffS = (uint32_t)(wn * 32 + ((lane >> 4) * 8) + (lane & 7)) * ALD
                            + (uint32_t)((lane >> 3) & 1) * 16;
    const uint32_t vRowOff = (uint32_t)(lane & 15) * ALD + (uint32_t)(lane >> 4) * 16;

    kvload(0, 0);

    for (int t = 0; t < S_ / 64; t++) {
        const int buf = t & 1;
        if (t + 1 < S_ / 64) {
            kvload(t + 1, buf ^ 1);
            asm volatile("cp.async.wait_group 1;" ::: "memory");
        } else {
            asm volatile("cp.async.wait_group 0;" ::: "memory");
        }
        __syncthreads();

        const uint32_t kHi = sb + KV_OFF + buf * KV_STAGE + KHI_O;
        const uint32_t kLo = sb + KV_OFF + buf * KV_STAGE + KLO_O;
        const uint32_t vBase = sb + KV_OFF + buf * KV_STAGE + V_O;

        // ---- S = Q K^T (3-term split) ----
        float acc_s[2][4][4];
#pragma unroll
        for (int i = 0; i < 2; i++)
#pragma unroll
            for (int j = 0; j < 4; j++)
#pragma unroll
                for (int q = 0; q < 4; q++) acc_s[i][j][q] = 0.0f;

#pragma unroll
        for (int ks = 0; ks < 8; ks++) {
            const uint32_t kso = (uint32_t)ks * 32;
            uint32_t ah[2][4], al[2][4];
#pragma unroll
            for (int mf = 0; mf < 2; mf++) {
                ldm4(ah[mf], sb + QHI_OFF + aRowOff + (uint32_t)mf * 16 * ALD + kso);
                ldm4(al[mf], sb + QLO_OFF + aRowOff + (uint32_t)mf * 16 * ALD + kso);
            }
#pragma unroll
            for (int nfp = 0; nfp < 2; nfp++) {
                uint32_t bh[4], bl[4];
                const uint32_t bo = bRowOffS + (uint32_t)nfp * 16 * ALD + kso;
                ldm4(bh, kHi + bo);
                ldm4(bl, kLo + bo);
#pragma unroll
                for (int p = 0; p < 2; p++) {
                    const int nf = nfp * 2 + p;
#pragma unroll
                    for (int mf = 0; mf < 2; mf++) {
                        mma16816(acc_s[mf][nf], ah[mf], bh[2 * p], bh[2 * p + 1]);
                        mma16816(acc_s[mf][nf], ah[mf], bl[2 * p], bl[2 * p + 1]);
                        mma16816(acc_s[mf][nf], al[mf], bh[2 * p], bh[2 * p + 1]);
                    }
                }
            }
        }

        // ---- store S (scaled) to smem fp32 ----
#pragma unroll
        for (int mf = 0; mf < 2; mf++) {
#pragma unroll
            for (int nf = 0; nf < 4; nf++) {
                const int r = wm * 32 + mf * 16 + (lane >> 2);
                const int c = wn * 32 + nf * 8 + (lane & 3) * 2;
                *(float2*)(smem + SP_OFF + (size_t)r * ALD + c * 4) =
                    make_float2(acc_s[mf][nf][0] * ATTN_SCALE,
                                acc_s[mf][nf][1] * ATTN_SCALE);
                *(float2*)(smem + SP_OFF + (size_t)(r + 8) * ALD + c * 4) =
                    make_float2(acc_s[mf][nf][2] * ATTN_SCALE,
                                acc_s[mf][nf][3] * ATTN_SCALE);
            }
        }
        __syncthreads();

        // ---- online softmax: 16 rows per warp; write P bf16 in place ----
#pragma unroll
        for (int rr = 0; rr < 16; rr++) {
            const int row = wid * 16 + rr;
            char* prow = smem + SP_OFF + (size_t)row * ALD;
            float s0 = ((float*)prow)[lane];
            float s1 = ((float*)prow)[32 + lane];
            float mx = fmaxf(s0, s1);
#pragma unroll
            for (int off = 16; off; off >>= 1)
                mx = fmaxf(mx, __shfl_xor_sync(0xffffffffu, mx, off));
            const float m_old = m_s[row];
            const float m_new = fmaxf(m_old, mx);
            const float p0 = __expf(s0 - m_new);
            const float p1 = __expf(s1 - m_new);
            float sum = p0 + p1;
#pragma unroll
            for (int off = 16; off; off >>= 1)
                sum += __shfl_xor_sync(0xffffffffu, sum, off);
            // all lanes have finished reading this row (shfl converged)
            ((__nv_bfloat16*)prow)[lane]      = __float2bfloat16(p0);
            ((__nv_bfloat16*)prow)[32 + lane] = __float2bfloat16(p1);
            if (lane == 0) {
                const float alpha = __expf(m_old - m_new);
                m_s[row] = m_new;
                l_s[row] = l_s[row] * alpha + sum;
                al_s[row] = alpha;
            }
        }
        __syncthreads();

        // ---- rescale O by alpha ----
#pragma unroll
        for (int mf = 0; mf < 2; mf++) {
            const int rbase = wm * 32 + mf * 16 + (lane >> 2);
            const float a0 = al_s[rbase];
            const float a1 = al_s[rbase + 8];
#pragma unroll
            for (int nf = 0; nf < 8; nf++) {
                acc_o[mf][nf][0] *= a0; acc_o[mf][nf][1] *= a0;
                acc_o[mf][nf][2] *= a1; acc_o[mf][nf][3] *= a1;
            }
        }

        // ---- O += P @ V ----
#pragma unroll
        for (int ks2 = 0; ks2 < 4; ks2++) {
            uint32_t pa[2][4];
#pragma unroll
            for (int mf = 0; mf < 2; mf++)
                ldm4(pa[mf], sb + SP_OFF + aRowOff + (uint32_t)mf * 16 * ALD
                           + (uint32_t)ks2 * 32);
#pragma unroll
            for (int nfp = 0; nfp < 4; nfp++) {
                uint32_t vr[4];
                ldm4t(vr, vBase + vRowOff + (uint32_t)ks2 * 16 * ALD
                        + (uint32_t)(wn * 64 + nfp * 16) * 2);
#pragma unroll
                for (int mf = 0; mf < 2; mf++) {
                    mma16816(acc_o[mf][nfp * 2],     pa[mf], vr[0], vr[1]);
                    mma16816(acc_o[mf][nfp * 2 + 1], pa[mf], vr[2], vr[3]);
                }
            }
        }
    }

    // ---- epilogue: normalize, add DP noise, split hi/lo, store ----
#pragma unroll
    for (int mf = 0; mf < 2; mf++) {
        const int rbase = wm * 32 + mf * 16 + (lane >> 2);
        const float inv0 = 1.0f / l_s[rbase];
        const float inv1 = 1.0f / l_s[rbase + 8];
#pragma unroll
        for (int nf = 0; nf < 8; nf++) {
            const int n = wn * 64 + nf * 8 + (lane & 3) * 2;
            const size_t g0 = (rowg0 + rbase) * E_ + hoff + n;
            const size_t g1 = (rowg0 + rbase + 8) * E_ + hoff + n;
            float2 n0 = *(const float2*)(Ng + g0);
            float2 n1 = *(const float2*)(Ng + g1);
            float v00 = acc_o[mf][nf][0] * inv0 + NSCALE * n0.x;
            float v01 = acc_o[mf][nf][1] * inv0 + NSCALE * n0.y;
            float v10 = acc_o[mf][nf][2] * inv1 + NSCALE * n1.x;
            float v11 = acc_o[mf][nf][3] * inv1 + NSCALE * n1.y;
            __nv_bfloat162 h0 = __floats2bfloat162_rn(v00, v01);
            __nv_bfloat162 h1 = __floats2bfloat162_rn(v10, v11);
            __nv_bfloat162 l0 = __floats2bfloat162_rn(
                v00 - __bfloat162float(h0.x), v01 - __bfloat162float(h0.y));
            __nv_bfloat162 l1 = __floats2bfloat162_rn(
                v10 - __bfloat162float(h1.x), v11 - __bfloat162float(h1.y));
            *(__nv_bfloat162*)(Ohi + g0) = h0;
            *(__nv_bfloat162*)(Ohi + g1) = h1;
            *(__nv_bfloat162*)(Olo + g0) = l0;
            *(__nv_bfloat162*)(Olo + g1) = l1;
        }
    }
}

// ---------------------------------------------------------------------------
// Launch
// ---------------------------------------------------------------------------
extern "C" void kernel_launch(void* const* d_in, const int* in_sizes, int n_in,
                              void* d_out, int out_size)
{
    const float* query = (const float*)d_in[0];
    const float* key_t = (const float*)d_in[1];
    const float* value = (const float*)d_in[2];
    const float* Wq    = (const float*)d_in[3];
    const float* bq    = (const float*)d_in[4];
    const float* Wk    = (const float*)d_in[5];
    const float* bk    = (const float*)d_in[6];
    const float* Wv    = (const float*)d_in[7];
    const float* bv    = (const float*)d_in[8];
    const float* Wo    = (const float*)d_in[9];
    const float* bo    = (const float*)d_in[10];
    const float* noise = (const float*)d_in[11];
    float* out = (float*)d_out;

    __nv_bfloat16 *qhi, *qlo, *khi, *klo, *vhi, *vlo, *xhi, *xlo, *whi, *wlo;
    cudaGetSymbolAddress((void**)&qhi, g_qhi);
    cudaGetSymbolAddress((void**)&qlo, g_qlo);
    cudaGetSymbolAddress((void**)&khi, g_khi);
    cudaGetSymbolAddress((void**)&klo, g_klo);
    cudaGetSymbolAddress((void**)&vhi, g_vhi);
    cudaGetSymbolAddress((void**)&vlo, g_vlo);
    cudaGetSymbolAddress((void**)&xhi, g_xhi);
    cudaGetSymbolAddress((void**)&xlo, g_xlo);
    cudaGetSymbolAddress((void**)&whi, g_whi);
    cudaGetSymbolAddress((void**)&wlo, g_wlo);

    cudaFuncSetAttribute(gemm_mma_kernel,
                         cudaFuncAttributeMaxDynamicSharedMemorySize, GEMM_SMEM);
    cudaFuncSetAttribute(attn_mma_kernel,
                         cudaFuncAttributeMaxDynamicSharedMemorySize, ATTN_SMEM);

    const size_t xTot = (size_t)MTOT * E_;
    const size_t wTot = (size_t)E_ * E_;
    const int convXBlocks = (int)((xTot / 8 + 255) / 256);
    const int convWBlocks = (int)((wTot / 8 + 255) / 256);
    dim3 gemmGrid(E_ / 128, MTOT / 128);   // (16, 64)

    // Q = query @ Wq^T + bq  -> bf16 hi/lo
    convert_split_kernel<<<convXBlocks, 256>>>(query, xhi, xlo, xTot);
    convert_split_kernel<<<convWBlocks, 256>>>(Wq, whi, wlo, wTot);
    gemm_mma_kernel<<<gemmGrid, 256, GEMM_SMEM>>>(xhi, xlo, whi, wlo, bq,
                                                  nullptr, qhi, qlo);
    // K = key_t @ Wk^T + bk
    convert_split_kernel<<<convXBlocks, 256>>>(key_t, xhi, xlo, xTot);
    convert_split_kernel<<<convWBlocks, 256>>>(Wk, whi, wlo, wTot);
    gemm_mma_kernel<<<gemmGrid, 256, GEMM_SMEM>>>(xhi, xlo, whi, wlo, bk,
                                                  nullptr, khi, klo);
    // V = value @ Wv^T + bv
    convert_split_kernel<<<convXBlocks, 256>>>(value, xhi, xlo, xTot);
    convert_split_kernel<<<convWBlocks, 256>>>(Wv, whi, wlo, wTot);
    gemm_mma_kernel<<<gemmGrid, 256, GEMM_SMEM>>>(xhi, xlo, whi, wlo, bv,
                                                  nullptr, vhi, vlo);

    // Flash attention + DP noise -> ctx hi/lo (into xhi/xlo)
    dim3 attnGrid(S_ / 128, H_, B_);       // (16, 16, 4)
    attn_mma_kernel<<<attnGrid, 256, ATTN_SMEM>>>(qhi, qlo, khi, klo, vhi,
                                                  noise, xhi, xlo);

    // out = ctx @ Wo^T + bo  (fp32)
    convert_split_kernel<<<convWBlocks, 256>>>(Wo, whi, wlo, wTot);
    gemm_mma_kernel<<<gemmGrid, 256, GEMM_SMEM>>>(xhi, xlo, whi, wlo, bo,
                                                  out, nullptr, nullptr);
}

// round 7
// speedup vs baseline: 2.7576x; 1.2381x over previous
#include <cuda_runtime.h>
#include <cuda_fp16.h>
#include <math.h>
#include <stdint.h>

// ---------------------------------------------------------------------------
// Problem constants
// ---------------------------------------------------------------------------
#define B_   4
#define S_   2048
#define E_   2048
#define H_   16
#define D_   128
#define MTOT (B_ * S_)

#define NSCALE 4.84480515f                 // sqrt(2*ln(1.25/1e-5))
#define ATTN_SCALE 0.08838834764831845f    // 1/sqrt(128)

// ---------------------------------------------------------------------------
// Scratch (__device__ globals; allocation-free rule)
// ---------------------------------------------------------------------------
__device__ __half g_xh[(size_t)MTOT * E_];
__device__ __half g_xl[(size_t)MTOT * E_];
__device__ __half g_wh[(size_t)E_ * E_];
__device__ __half g_wl[(size_t)E_ * E_];
__device__ __half g_qh[(size_t)MTOT * E_];
__device__ __half g_ql[(size_t)MTOT * E_];
__device__ __half g_kh[(size_t)MTOT * E_];
__device__ __half g_vh[(size_t)MTOT * E_];
__device__ __half g_ch[(size_t)MTOT * E_];
__device__ __half g_cl[(size_t)MTOT * E_];

// ---------------------------------------------------------------------------
// PTX helpers (arch-generic: cp.async, ldmatrix, mma.sync fp16)
// ---------------------------------------------------------------------------
__device__ __forceinline__ uint32_t smem_u32(const void* p) {
    uint32_t a;
    asm("{ .reg .u64 t; cvta.to.shared.u64 t, %1; cvt.u32.u64 %0, t; }"
        : "=r"(a) : "l"(p));
    return a;
}

__device__ __forceinline__ void cp16(uint32_t dst, const void* src) {
    asm volatile("cp.async.cg.shared.global [%0], [%1], 16;"
                 :: "r"(dst), "l"(src) : "memory");
}

__device__ __forceinline__ void ldm4(uint32_t* r, uint32_t addr) {
    asm volatile("ldmatrix.sync.aligned.m8n8.x4.shared.b16 {%0,%1,%2,%3}, [%4];"
                 : "=r"(r[0]), "=r"(r[1]), "=r"(r[2]), "=r"(r[3])
                 : "r"(addr));
}

__device__ __forceinline__ void ldm4t(uint32_t* r, uint32_t addr) {
    asm volatile("ldmatrix.sync.aligned.m8n8.x4.trans.shared.b16 {%0,%1,%2,%3}, [%4];"
                 : "=r"(r[0]), "=r"(r[1]), "=r"(r[2]), "=r"(r[3])
                 : "r"(addr));
}

__device__ __forceinline__ void mmah(float* c, const uint32_t* a,
                                     uint32_t b0, uint32_t b1) {
    asm volatile(
        "mma.sync.aligned.m16n8k16.row.col.f32.f16.f16.f32 "
        "{%0,%1,%2,%3}, {%4,%5,%6,%7}, {%8,%9}, {%0,%1,%2,%3};"
        : "+f"(c[0]), "+f"(c[1]), "+f"(c[2]), "+f"(c[3])
        : "r"(a[0]), "r"(a[1]), "r"(a[2]), "r"(a[3]), "r"(b0), "r"(b1));
}

// ---------------------------------------------------------------------------
// Converts
// ---------------------------------------------------------------------------
__global__ void convert_split_h(const float* __restrict__ in,
                                __half* __restrict__ hi,
                                __half* __restrict__ lo, size_t total)
{
    size_t idx = ((size_t)blockIdx.x * blockDim.x + threadIdx.x) * 8;
    if (idx >= total) return;
    float4 a = *(const float4*)(in + idx);
    float4 b = *(const float4*)(in + idx + 4);
    float v[8] = {a.x, a.y, a.z, a.w, b.x, b.y, b.z, b.w};
    __half h8[8], l8[8];
#pragma unroll
    for (int i = 0; i < 8; i++) {
        __half h = __float2half_rn(v[i]);
        h8[i] = h;
        l8[i] = __float2half_rn(v[i] - __half2float(h));
    }
    *(uint4*)(hi + idx) = *(uint4*)h8;
    *(uint4*)(lo + idx) = *(uint4*)l8;
}

__global__ void convert_h(const float* __restrict__ in,
                          __half* __restrict__ hi, size_t total)
{
    size_t idx = ((size_t)blockIdx.x * blockDim.x + threadIdx.x) * 8;
    if (idx >= total) return;
    float4 a = *(const float4*)(in + idx);
    float4 b = *(const float4*)(in + idx + 4);
    float v[8] = {a.x, a.y, a.z, a.w, b.x, b.y, b.z, b.w};
    __half h8[8];
#pragma unroll
    for (int i = 0; i < 8; i++) h8[i] = __float2half_rn(v[i]);
    *(uint4*)(hi + idx) = *(uint4*)h8;
}

// ---------------------------------------------------------------------------
// 2-term fp16 GEMM-NT + bias: out = Xh*Wh + Xl*Wh (+ bias).
// CTA 128x128, Ktile 32, 8 warps, 3-stage cp.async pipeline, 2 CTAs/SM.
// Epilogue: fp16 hi(+optional lo) outputs.
// ---------------------------------------------------------------------------
#define LDB     80
#define ABYTES  (128 * LDB)          // 10240
#define STAGE2  (3 * ABYTES)         // 30720 (Ah|Al|Bh)
#define GEMM2_SMEM (3 * STAGE2)      // 92160
#define KTILES  64

__global__ __launch_bounds__(256, 2)
void gemm2_kernel(const __half* __restrict__ Ah, const __half* __restrict__ Al,
                  const __half* __restrict__ Bh, const float* __restrict__ bias,
                  __half* __restrict__ outHi, __half* __restrict__ outLo)
{
    extern __shared__ char smem[];
    const uint32_t sb = smem_u32(smem);
    const int tid  = threadIdx.x;
    const int wid  = tid >> 5;
    const int lane = tid & 31;
    const int nb = blockIdx.x, mb = blockIdx.y;
    const int wm = wid >> 1, wn = wid & 1;

    const __half* pAh = Ah + (size_t)(mb * 128) * 2048;
    const __half* pAl = Al + (size_t)(mb * 128) * 2048;
    const __half* pBh = Bh + (size_t)(nb * 128) * 2048;

    const int lr = tid >> 1;
    const int lc = (tid & 1) * 2;

    auto load_tile = [&](int kt, int buf) {
        const uint32_t s = sb + buf * STAGE2;
        const size_t go = (size_t)lr * 2048 + (size_t)kt * 32 + (size_t)lc * 8;
        const uint32_t so = (uint32_t)lr * LDB + (uint32_t)lc * 16;
#pragma unroll
        for (int j = 0; j < 2; j++) {
            cp16(s + so + j * 16,              pAh + go + j * 8);
            cp16(s + ABYTES     + so + j * 16, pAl + go + j * 8);
            cp16(s + 2 * ABYTES + so + j * 16, pBh + go + j * 8);
        }
        asm volatile("cp.async.commit_group;" ::: "memory");
    };

    float acc[2][8][4];
#pragma unroll
    for (int i = 0; i < 2; i++)
#pragma unroll
        for (int j = 0; j < 8; j++)
#pragma unroll
            for (int t = 0; t < 4; t++) acc[i][j][t] = 0.0f;

    const uint32_t aRowOff = (uint32_t)(wm * 32 + (lane & 15)) * LDB
                           + (uint32_t)(lane >> 4) * 16;
    const uint32_t bRowOff = (uint32_t)(wn * 64 + ((lane >> 4) * 8) + (lane & 7)) * LDB
                           + (uint32_t)((lane >> 3) & 1) * 16;

    load_tile(0, 0);
    load_tile(1, 1);
    int buf = 0;

    for (int kt = 0; kt < KTILES; kt++) {
        if (kt + 1 < KTILES) asm volatile("cp.async.wait_group 1;" ::: "memory");
        else                 asm volatile("cp.async.wait_group 0;" ::: "memory");
        __syncthreads();
        if (kt + 2 < KTILES) {
            int nbuf = buf + 2; if (nbuf >= 3) nbuf -= 3;
            load_tile(kt + 2, nbuf);
        }

        const uint32_t aHi = sb + buf * STAGE2;
        const uint32_t aLo = aHi + ABYTES;
        const uint32_t bHi = aHi + 2 * ABYTES;

#pragma unroll
        for (int ks = 0; ks < 2; ks++) {
            const uint32_t kso = (uint32_t)ks * 32;
            uint32_t ah[2][4], al[2][4];
#pragma unroll
            for (int mf = 0; mf < 2; mf++) {
                ldm4(ah[mf], aHi + aRowOff + (uint32_t)mf * 16 * LDB + kso);
                ldm4(al[mf], aLo + aRowOff + (uint32_t)mf * 16 * LDB + kso);
            }
#pragma unroll
            for (int nfp = 0; nfp < 4; nfp++) {
                uint32_t bh[4];
                ldm4(bh, bHi + bRowOff + (uint32_t)nfp * 16 * LDB + kso);
#pragma unroll
                for (int p = 0; p < 2; p++) {
                    const int nf = nfp * 2 + p;
#pragma unroll
                    for (int mf = 0; mf < 2; mf++) {
                        mmah(acc[mf][nf], ah[mf], bh[2 * p], bh[2 * p + 1]);
                        mmah(acc[mf][nf], al[mf], bh[2 * p], bh[2 * p + 1]);
                    }
                }
            }
        }
        buf++; if (buf >= 3) buf -= 3;
    }

    const int mBase = mb * 128 + wm * 32 + (lane >> 2);
    const int nBase = nb * 128 + wn * 64 + (lane & 3) * 2;
#pragma unroll
    for (int mf = 0; mf < 2; mf++) {
#pragma unroll
        for (int nf = 0; nf < 8; nf++) {
            const int m = mBase + mf * 16;
            const int n = nBase + nf * 8;
            const float2 bb = *(const float2*)(bias + n);
            float v00 = acc[mf][nf][0] + bb.x;
            float v01 = acc[mf][nf][1] + bb.y;
            float v10 = acc[mf][nf][2] + bb.x;
            float v11 = acc[mf][nf][3] + bb.y;
            __half h00 = __float2half_rn(v00), h01 = __float2half_rn(v01);
            __half h10 = __float2half_rn(v10), h11 = __float2half_rn(v11);
            *(__half2*)(outHi + (size_t)m * 2048 + n)       = __halves2half2(h00, h01);
            *(__half2*)(outHi + (size_t)(m + 8) * 2048 + n) = __halves2half2(h10, h11);
            if (outLo) {
                __half l00 = __float2half_rn(v00 - __half2float(h00));
                __half l01 = __float2half_rn(v01 - __half2float(h01));
                __half l10 = __float2half_rn(v10 - __half2float(h10));
                __half l11 = __float2half_rn(v11 - __half2float(h11));
                *(__half2*)(outLo + (size_t)m * 2048 + n)       = __halves2half2(l00, l01);
                *(__half2*)(outLo + (size_t)(m + 8) * 2048 + n) = __halves2half2(l10, l11);
            }
        }
    }
}

// ---------------------------------------------------------------------------
// 3-term fp16 GEMM-NT + bias (final projection, fp32 out). 2-stage pipeline.
// ---------------------------------------------------------------------------
#define STAGE3  (4 * ABYTES)         // 40960 (Ah|Al|Bh|Bl)
#define GEMM3_SMEM (2 * STAGE3)      // 81920

__global__ __launch_bounds__(256, 2)
void gemm3_kernel(const __half* __restrict__ Ah, const __half* __restrict__ Al,
                  const __half* __restrict__ Bh, const __half* __restrict__ Bl,
                  const float* __restrict__ bias, float* __restrict__ out)
{
    extern __shared__ char smem[];
    const uint32_t sb = smem_u32(smem);
    const int tid  = threadIdx.x;
    const int wid  = tid >> 5;
    const int lane = tid & 31;
    const int nb = blockIdx.x, mb = blockIdx.y;
    const int wm = wid >> 1, wn = wid & 1;

    const __half* pAh = Ah + (size_t)(mb * 128) * 2048;
    const __half* pAl = Al + (size_t)(mb * 128) * 2048;
    const __half* pBh = Bh + (size_t)(nb * 128) * 2048;
    const __half* pBl = Bl + (size_t)(nb * 128) * 2048;

    const int lr = tid >> 1;
    const int lc = (tid & 1) * 2;

    auto load_tile = [&](int kt, int buf) {
        const uint32_t s = sb + buf * STAGE3;
        const size_t go = (size_t)lr * 2048 + (size_t)kt * 32 + (size_t)lc * 8;
        const uint32_t so = (uint32_t)lr * LDB + (uint32_t)lc * 16;
#pragma unroll
        for (int j = 0; j < 2; j++) {
            cp16(s + so + j * 16,              pAh + go + j * 8);
            cp16(s + ABYTES     + so + j * 16, pAl + go + j * 8);
            cp16(s + 2 * ABYTES + so + j * 16, pBh + go + j * 8);
            cp16(s + 3 * ABYTES + so + j * 16, pBl + go + j * 8);
        }
        asm volatile("cp.async.commit_group;" ::: "memory");
    };

    float acc[2][8][4];
#pragma unroll
    for (int i = 0; i < 2; i++)
#pragma unroll
        for (int j = 0; j < 8; j++)
#pragma unroll
            for (int t = 0; t < 4; t++) acc[i][j][t] = 0.0f;

    const uint32_t aRowOff = (uint32_t)(wm * 32 + (lane & 15)) * LDB
                           + (uint32_t)(lane >> 4) * 16;
    const uint32_t bRowOff = (uint32_t)(wn * 64 + ((lane >> 4) * 8) + (lane & 7)) * LDB
                           + (uint32_t)((lane >> 3) & 1) * 16;

    load_tile(0, 0);

    for (int kt = 0; kt < KTILES; kt++) {
        const int buf = kt & 1;
        if (kt + 1 < KTILES) {
            load_tile(kt + 1, buf ^ 1);
            asm volatile("cp.async.wait_group 1;" ::: "memory");
        } else {
            asm volatile("cp.async.wait_group 0;" ::: "memory");
        }
        __syncthreads();

        const uint32_t aHi = sb + buf * STAGE3;
        const uint32_t aLo = aHi + ABYTES;
        const uint32_t bHi = aHi + 2 * ABYTES;
        const uint32_t bLo = aHi + 3 * ABYTES;

#pragma unroll
        for (int ks = 0; ks < 2; ks++) {
            const uint32_t kso = (uint32_t)ks * 32;
            uint32_t ah[2][4], al[2][4];
#pragma unroll
            for (int mf = 0; mf < 2; mf++) {
                ldm4(ah[mf], aHi + aRowOff + (uint32_t)mf * 16 * LDB + kso);
                ldm4(al[mf], aLo + aRowOff + (uint32_t)mf * 16 * LDB + kso);
            }
#pragma unroll
            for (int nfp = 0; nfp < 4; nfp++) {
                uint32_t bh[4], bl[4];
                const uint32_t bo = bRowOff + (uint32_t)nfp * 16 * LDB + kso;
                ldm4(bh, bHi + bo);
                ldm4(bl, bLo + bo);
#pragma unroll
                for (int p = 0; p < 2; p++) {
                    const int nf = nfp * 2 + p;
#pragma unroll
                    for (int mf = 0; mf < 2; mf++) {
                        mmah(acc[mf][nf], ah[mf], bh[2 * p], bh[2 * p + 1]);
                        mmah(acc[mf][nf], ah[mf], bl[2 * p], bl[2 * p + 1]);
                        mmah(acc[mf][nf], al[mf], bh[2 * p], bh[2 * p + 1]);
                    }
                }
            }
        }
        __syncthreads();
    }

    const int mBase = mb * 128 + wm * 32 + (lane >> 2);
    const int nBase = nb * 128 + wn * 64 + (lane & 3) * 2;
#pragma unroll
    for (int mf = 0; mf < 2; mf++) {
#pragma unroll
        for (int nf = 0; nf < 8; nf++) {
            const int m = mBase + mf * 16;
            const int n = nBase + nf * 8;
            const float2 bb = *(const float2*)(bias + n);
            *(float2*)(out + (size_t)m * 2048 + n) =
                make_float2(acc[mf][nf][0] + bb.x, acc[mf][nf][1] + bb.y);
            *(float2*)(out + (size_t)(m + 8) * 2048 + n) =
                make_float2(acc[mf][nf][2] + bb.x, acc[mf][nf][3] + bb.y);
        }
    }
}

// ---------------------------------------------------------------------------
// fp16 tensor-core flash attention + fused DP noise.
// S = Qh*Kh + Ql*Kh (2-term); P fp16 in place; O += P*V (ldm.trans).
// Epilogue: ctx hi/lo fp16.
// ---------------------------------------------------------------------------
#define ALD      272
#define QH_OFF   0
#define QL_OFF   34816
#define KV_OFF   69632
#define KV_STAGE 34816
#define KH_O     0
#define V_O      17408
#define SP_OFF   139264
#define MS_OFF   174080
#define LS_OFF   174592
#define AL_OFF   175104
#define ATTN_SMEM 175616

__global__ __launch_bounds__(256, 1)
void attn_mma_kernel(const __half* __restrict__ Qh, const __half* __restrict__ Ql,
                     const __half* __restrict__ Kh, const __half* __restrict__ Vh,
                     const float* __restrict__ Ng,
                     __half* __restrict__ Ohi, __half* __restrict__ Olo)
{
    extern __shared__ char smem[];
    const uint32_t sb = smem_u32(smem);
    const int tid  = threadIdx.x;
    const int wid  = tid >> 5;
    const int lane = tid & 31;
    const int wm = wid >> 1, wn = wid & 1;

    const int b  = blockIdx.z;
    const int h  = blockIdx.y;
    const int q0 = blockIdx.x * 128;

    const size_t rowg0 = (size_t)b * S_ + q0;
    const size_t brow0 = (size_t)b * S_;
    const size_t hoff  = (size_t)h * D_;

    float* m_s  = (float*)(smem + MS_OFF);
    float* l_s  = (float*)(smem + LS_OFF);
    float* al_s = (float*)(smem + AL_OFF);

    // ---- load Q hi/lo ----
    {
        const int r  = tid >> 1;
        const int cb = (tid & 1) * 8;
        const __half* gqh = Qh + (rowg0 + r) * E_ + hoff + cb * 8;
        const __half* gql = Ql + (rowg0 + r) * E_ + hoff + cb * 8;
        const uint32_t sq = (uint32_t)r * ALD + (uint32_t)cb * 16;
#pragma unroll
        for (int j = 0; j < 8; j++) {
            cp16(sb + QH_OFF + sq + j * 16, gqh + j * 8);
            cp16(sb + QL_OFF + sq + j * 16, gql + j * 8);
        }
        asm volatile("cp.async.commit_group;" ::: "memory");
    }
    if (tid < 128) { m_s[tid] = -INFINITY; l_s[tid] = 0.0f; }

    const int kr  = tid >> 2;
    const int kcb = (tid & 3) * 4;
    auto kvload = [&](int t, int buf) {
        const uint32_t s = sb + KV_OFF + buf * KV_STAGE;
        const size_t grow = (brow0 + t * 64 + kr) * E_ + hoff + kcb * 8;
        const uint32_t so = (uint32_t)kr * ALD + (uint32_t)kcb * 16;
#pragma unroll
        for (int j = 0; j < 4; j++) {
            cp16(s + KH_O + so + j * 16, Kh + grow + j * 8);
            cp16(s + V_O  + so + j * 16, Vh + grow + j * 8);
        }
        asm volatile("cp.async.commit_group;" ::: "memory");
    };

    float acc_o[2][8][4];
#pragma unroll
    for (int i = 0; i < 2; i++)
#pragma unroll
        for (int j = 0; j < 8; j++)
#pragma unroll
            for (int t = 0; t < 4; t++) acc_o[i][j][t] = 0.0f;

    const uint32_t aRowOff = (uint32_t)(wm * 32 + (lane & 15)) * ALD
                           + (uint32_t)(lane >> 4) * 16;
    const uint32_t bRowOffS = (uint32_t)(wn * 32 + ((lane >> 4) * 8) + (lane & 7)) * ALD
                            + (uint32_t)((lane >> 3) & 1) * 16;
    const uint32_t vRowOff = (uint32_t)(lane & 15) * ALD + (uint32_t)(lane >> 4) * 16;

    kvload(0, 0);

    for (int t = 0; t < S_ / 64; t++) {
        const int buf = t & 1;
        if (t + 1 < S_ / 64) {
            kvload(t + 1, buf ^ 1);
            asm volatile("cp.async.wait_group 1;" ::: "memory");
        } else {
            asm volatile("cp.async.wait_group 0;" ::: "memory");
        }
        __syncthreads();

        const uint32_t kHi   = sb + KV_OFF + buf * KV_STAGE + KH_O;
        const uint32_t vBase = sb + KV_OFF + buf * KV_STAGE + V_O;

        // ---- S = Q K^T (2-term fp16) ----
        float acc_s[2][4][4];
#pragma unroll
        for (int i = 0; i < 2; i++)
#pragma unroll
            for (int j = 0; j < 4; j++)
#pragma unroll
                for (int q = 0; q < 4; q++) acc_s[i][j][q] = 0.0f;

#pragma unroll
        for (int ks = 0; ks < 8; ks++) {
            const uint32_t kso = (uint32_t)ks * 32;
            uint32_t ah[2][4], al[2][4];
#pragma unroll
            for (int mf = 0; mf < 2; mf++) {
                ldm4(ah[mf], sb + QH_OFF + aRowOff + (uint32_t)mf * 16 * ALD + kso);
                ldm4(al[mf], sb + QL_OFF + aRowOff + (uint32_t)mf * 16 * ALD + kso);
            }
#pragma unroll
            for (int nfp = 0; nfp < 2; nfp++) {
                uint32_t bh[4];
                ldm4(bh, kHi + bRowOffS + (uint32_t)nfp * 16 * ALD + kso);
#pragma unroll
                for (int p = 0; p < 2; p++) {
                    const int nf = nfp * 2 + p;
#pragma unroll
                    for (int mf = 0; mf < 2; mf++) {
                        mmah(acc_s[mf][nf], ah[mf], bh[2 * p], bh[2 * p + 1]);
                        mmah(acc_s[mf][nf], al[mf], bh[2 * p], bh[2 * p + 1]);
                    }
                }
            }
        }

        // ---- store S (scaled) to smem fp32 ----
#pragma unroll
        for (int mf = 0; mf < 2; mf++) {
#pragma unroll
            for (int nf = 0; nf < 4; nf++) {
                const int r = wm * 32 + mf * 16 + (lane >> 2);
                const int c = wn * 32 + nf * 8 + (lane & 3) * 2;
                *(float2*)(smem + SP_OFF + (size_t)r * ALD + c * 4) =
                    make_float2(acc_s[mf][nf][0] * ATTN_SCALE,
                                acc_s[mf][nf][1] * ATTN_SCALE);
                *(float2*)(smem + SP_OFF + (size_t)(r + 8) * ALD + c * 4) =
                    make_float2(acc_s[mf][nf][2] * ATTN_SCALE,
                                acc_s[mf][nf][3] * ATTN_SCALE);
            }
        }
        __syncthreads();

        // ---- online softmax; P fp16 in place ----
#pragma unroll
        for (int rr = 0; rr < 16; rr++) {
            const int row = wid * 16 + rr;
            char* prow = smem + SP_OFF + (size_t)row * ALD;
            float s0 = ((float*)prow)[lane];
            float s1 = ((float*)prow)[32 + lane];
            float mx = fmaxf(s0, s1);
#pragma unroll
            for (int off = 16; off; off >>= 1)
                mx = fmaxf(mx, __shfl_xor_sync(0xffffffffu, mx, off));
            const float m_old = m_s[row];
            const float m_new = fmaxf(m_old, mx);
            const float p0 = __expf(s0 - m_new);
            const float p1 = __expf(s1 - m_new);
            float sum = p0 + p1;
#pragma unroll
            for (int off = 16; off; off >>= 1)
                sum += __shfl_xor_sync(0xffffffffu, sum, off);
            ((__half*)prow)[lane]      = __float2half_rn(p0);
            ((__half*)prow)[32 + lane] = __float2half_rn(p1);
            if (lane == 0) {
                const float alpha = __expf(m_old - m_new);
                m_s[row] = m_new;
                l_s[row] = l_s[row] * alpha + sum;
                al_s[row] = alpha;
            }
        }
        __syncthreads();

        // ---- rescale O ----
#pragma unroll
        for (int mf = 0; mf < 2; mf++) {
            const int rbase = wm * 32 + mf * 16 + (lane >> 2);
            const float a0 = al_s[rbase];
            const float a1 = al_s[rbase + 8];
#pragma unroll
            for (int nf = 0; nf < 8; nf++) {
                acc_o[mf][nf][0] *= a0; acc_o[mf][nf][1] *= a0;
                acc_o[mf][nf][2] *= a1; acc_o[mf][nf][3] *= a1;
            }
        }

        // ---- O += P @ V ----
#pragma unroll
        for (int ks2 = 0; ks2 < 4; ks2++) {
            uint32_t pa[2][4];
#pragma unroll
            for (int mf = 0; mf < 2; mf++)
                ldm4(pa[mf], sb + SP_OFF + aRowOff + (uint32_t)mf * 16 * ALD
                           + (uint32_t)ks2 * 32);
#pragma unroll
            for (int nfp = 0; nfp < 4; nfp++) {
                uint32_t vr[4];
                ldm4t(vr, vBase + vRowOff + (uint32_t)ks2 * 16 * ALD
                        + (uint32_t)(wn * 64 + nfp * 16) * 2);
#pragma unroll
                for (int mf = 0; mf < 2; mf++) {
                    mmah(acc_o[mf][nfp * 2],     pa[mf], vr[0], vr[1]);
                    mmah(acc_o[mf][nfp * 2 + 1], pa[mf], vr[2], vr[3]);
                }
            }
        }
    }

    // ---- epilogue: normalize, DP noise, split fp16 hi/lo ----
#pragma unroll
    for (int mf = 0; mf < 2; mf++) {
        const int rbase = wm * 32 + mf * 16 + (lane >> 2);
        const float inv0 = 1.0f / l_s[rbase];
        const float inv1 = 1.0f / l_s[rbase + 8];
#pragma unroll
        for (int nf = 0; nf < 8; nf++) {
            const int n = wn * 64 + nf * 8 + (lane & 3) * 2;
            const size_t g0 = (rowg0 + rbase) * E_ + hoff + n;
            const size_t g1 = (rowg0 + rbase + 8) * E_ + hoff + n;
            float2 n0 = *(const float2*)(Ng + g0);
            float2 n1 = *(const float2*)(Ng + g1);
            float v00 = acc_o[mf][nf][0] * inv0 + NSCALE * n0.x;
            float v01 = acc_o[mf][nf][1] * inv0 + NSCALE * n0.y;
            float v10 = acc_o[mf][nf][2] * inv1 + NSCALE * n1.x;
            float v11 = acc_o[mf][nf][3] * inv1 + NSCALE * n1.y;
            __half h00 = __float2half_rn(v00), h01 = __float2half_rn(v01);
            __half h10 = __float2half_rn(v10), h11 = __float2half_rn(v11);
            *(__half2*)(Ohi + g0) = __halves2half2(h00, h01);
            *(__half2*)(Ohi + g1) = __halves2half2(h10, h11);
            *(__half2*)(Olo + g0) = __halves2half2(
                __float2half_rn(v00 - __half2float(h00)),
                __float2half_rn(v01 - __half2float(h01)));
            *(__half2*)(Olo + g1) = __halves2half2(
                __float2half_rn(v10 - __half2float(h10)),
                __float2half_rn(v11 - __half2float(h11)));
        }
    }
}

// ---------------------------------------------------------------------------
// Launch
// ---------------------------------------------------------------------------
extern "C" void kernel_launch(void* const* d_in, const int* in_sizes, int n_in,
                              void* d_out, int out_size)
{
    const float* query = (const float*)d_in[0];
    const float* key_t = (const float*)d_in[1];
    const float* value = (const float*)d_in[2];
    const float* Wq    = (const float*)d_in[3];
    const float* bq    = (const float*)d_in[4];
    const float* Wk    = (const float*)d_in[5];
    const float* bk    = (const float*)d_in[6];
    const float* Wv    = (const float*)d_in[7];
    const float* bv    = (const float*)d_in[8];
    const float* Wo    = (const float*)d_in[9];
    const float* bo    = (const float*)d_in[10];
    const float* noise = (const float*)d_in[11];
    float* out = (float*)d_out;

    __half *xh, *xl, *wh, *wl, *qh, *ql, *kh, *vh, *ch, *cl;
    cudaGetSymbolAddress((void**)&xh, g_xh);
    cudaGetSymbolAddress((void**)&xl, g_xl);
    cudaGetSymbolAddress((void**)&wh, g_wh);
    cudaGetSymbolAddress((void**)&wl, g_wl);
    cudaGetSymbolAddress((void**)&qh, g_qh);
    cudaGetSymbolAddress((void**)&ql, g_ql);
    cudaGetSymbolAddress((void**)&kh, g_kh);
    cudaGetSymbolAddress((void**)&vh, g_vh);
    cudaGetSymbolAddress((void**)&ch, g_ch);
    cudaGetSymbolAddress((void**)&cl, g_cl);

    cudaFuncSetAttribute(gemm2_kernel,
                         cudaFuncAttributeMaxDynamicSharedMemorySize, GEMM2_SMEM);
    cudaFuncSetAttribute(gemm3_kernel,
                         cudaFuncAttributeMaxDynamicSharedMemorySize, GEMM3_SMEM);
    cudaFuncSetAttribute(attn_mma_kernel,
                         cudaFuncAttributeMaxDynamicSharedMemorySize, ATTN_SMEM);

    const size_t xTot = (size_t)MTOT * E_;
    const size_t wTot = (size_t)E_ * E_;
    const int cX = (int)((xTot / 8 + 255) / 256);
    const int cW = (int)((wTot / 8 + 255) / 256);
    dim3 gemmGrid(E_ / 128, MTOT / 128);   // (16, 64)

    // Q = query @ Wq^T + bq  -> fp16 hi+lo
    convert_split_h<<<cX, 256>>>(query, xh, xl, xTot);
    convert_h<<<cW, 256>>>(Wq, wh, wTot);
    gemm2_kernel<<<gemmGrid, 256, GEMM2_SMEM>>>(xh, xl, wh, bq, qh, ql);

    // K = key_t @ Wk^T + bk  -> fp16 hi only
    convert_split_h<<<cX, 256>>>(key_t, xh, xl, xTot);
    convert_h<<<cW, 256>>>(Wk, wh, wTot);
    gemm2_kernel<<<gemmGrid, 256, GEMM2_SMEM>>>(xh, xl, wh, bk, kh, nullptr);

    // V = value @ Wv^T + bv  -> fp16 hi only
    convert_split_h<<<cX, 256>>>(value, xh, xl, xTot);
    convert_h<<<cW, 256>>>(Wv, wh, wTot);
    gemm2_kernel<<<gemmGrid, 256, GEMM2_SMEM>>>(xh, xl, wh, bv, vh, nullptr);

    // Attention + DP noise -> ctx hi/lo
    dim3 attnGrid(S_ / 128, H_, B_);       // (16, 16, 4)
    attn_mma_kernel<<<attnGrid, 256, ATTN_SMEM>>>(qh, ql, kh, vh, noise, ch, cl);

    // out = ctx @ Wo^T + bo  (3-term, fp32 out)
    convert_split_h<<<cW, 256>>>(Wo, wh, wl, wTot);
    gemm3_kernel<<<gemmGrid, 256, GEMM3_SMEM>>>(ch, cl, wh, wl, bo, out);
}

// round 8
// speedup vs baseline: 3.6178x; 1.3119x over previous
#include <cuda_runtime.h>
#include <cuda_fp16.h>
#include <math.h>
#include <stdint.h>

// ---------------------------------------------------------------------------
// Problem constants
// ---------------------------------------------------------------------------
#define B_   4
#define S_   2048
#define E_   2048
#define H_   16
#define D_   128
#define MTOT (B_ * S_)

#define NSCALE 4.84480515f                 // sqrt(2*ln(1.25/1e-5))
#define ATTN_SCALE 0.08838834764831845f    // 1/sqrt(128)

// ---------------------------------------------------------------------------
// Scratch (__device__ globals)
// ---------------------------------------------------------------------------
__device__ __half g_xh[(size_t)MTOT * E_];
__device__ __half g_wh[(size_t)E_ * E_];
__device__ __half g_qh[(size_t)MTOT * E_];
__device__ __half g_kh[(size_t)MTOT * E_];
__device__ __half g_vh[(size_t)MTOT * E_];
__device__ __half g_ch[(size_t)MTOT * E_];
__device__ __half g_cl[(size_t)MTOT * E_];

// ---------------------------------------------------------------------------
// PTX helpers (arch-generic: cp.async, ldmatrix, mma.sync fp16)
// ---------------------------------------------------------------------------
__device__ __forceinline__ uint32_t smem_u32(const void* p) {
    uint32_t a;
    asm("{ .reg .u64 t; cvta.to.shared.u64 t, %1; cvt.u32.u64 %0, t; }"
        : "=r"(a) : "l"(p));
    return a;
}

__device__ __forceinline__ void cp16(uint32_t dst, const void* src) {
    asm volatile("cp.async.cg.shared.global [%0], [%1], 16;"
                 :: "r"(dst), "l"(src) : "memory");
}

__device__ __forceinline__ void ldm4(uint32_t* r, uint32_t addr) {
    asm volatile("ldmatrix.sync.aligned.m8n8.x4.shared.b16 {%0,%1,%2,%3}, [%4];"
                 : "=r"(r[0]), "=r"(r[1]), "=r"(r[2]), "=r"(r[3])
                 : "r"(addr));
}

__device__ __forceinline__ void ldm4t(uint32_t* r, uint32_t addr) {
    asm volatile("ldmatrix.sync.aligned.m8n8.x4.trans.shared.b16 {%0,%1,%2,%3}, [%4];"
                 : "=r"(r[0]), "=r"(r[1]), "=r"(r[2]), "=r"(r[3])
                 : "r"(addr));
}

__device__ __forceinline__ void mmah(float* c, const uint32_t* a,
                                     uint32_t b0, uint32_t b1) {
    asm volatile(
        "mma.sync.aligned.m16n8k16.row.col.f32.f16.f16.f32 "
        "{%0,%1,%2,%3}, {%4,%5,%6,%7}, {%8,%9}, {%0,%1,%2,%3};"
        : "+f"(c[0]), "+f"(c[1]), "+f"(c[2]), "+f"(c[3])
        : "r"(a[0]), "r"(a[1]), "r"(a[2]), "r"(a[3]), "r"(b0), "r"(b1));
}

// ---------------------------------------------------------------------------
// Convert: fp32 -> fp16
// ---------------------------------------------------------------------------
__global__ void convert_h(const float* __restrict__ in,
                          __half* __restrict__ hi, size_t total)
{
    size_t idx = ((size_t)blockIdx.x * blockDim.x + threadIdx.x) * 8;
    if (idx >= total) return;
    float4 a = *(const float4*)(in + idx);
    float4 b = *(const float4*)(in + idx + 4);
    float v[8] = {a.x, a.y, a.z, a.w, b.x, b.y, b.z, b.w};
    __half h8[8];
#pragma unroll
    for (int i = 0; i < 8; i++) h8[i] = __float2half_rn(v[i]);
    *(uint4*)(hi + idx) = *(uint4*)h8;
}

// ---------------------------------------------------------------------------
// 1-term fp16 GEMM-NT + bias (QKV projections): out = Xh*Wh + bias, fp16 out.
// CTA 128x128, Ktile 32, 8 warps, 3-stage cp.async pipeline, 2 CTAs/SM.
// ---------------------------------------------------------------------------
#define LDB     80
#define ABYTES  (128 * LDB)          // 10240
#define STAGE1  (2 * ABYTES)         // 20480 (A|B)
#define GEMM1_SMEM (3 * STAGE1)      // 61440
#define KTILES  64

__global__ __launch_bounds__(256, 2)
void gemm1_kernel(const __half* __restrict__ Ah, const __half* __restrict__ Bh,
                  const float* __restrict__ bias, __half* __restrict__ outH)
{
    extern __shared__ char smem[];
    const uint32_t sb = smem_u32(smem);
    const int tid  = threadIdx.x;
    const int wid  = tid >> 5;
    const int lane = tid & 31;
    const int nb = blockIdx.x, mb = blockIdx.y;
    const int wm = wid >> 1, wn = wid & 1;

    const __half* pAh = Ah + (size_t)(mb * 128) * 2048;
    const __half* pBh = Bh + (size_t)(nb * 128) * 2048;

    const int lr = tid >> 1;
    const int lc = (tid & 1) * 2;

    auto load_tile = [&](int kt, int buf) {
        const uint32_t s = sb + buf * STAGE1;
        const size_t go = (size_t)lr * 2048 + (size_t)kt * 32 + (size_t)lc * 8;
        const uint32_t so = (uint32_t)lr * LDB + (uint32_t)lc * 16;
#pragma unroll
        for (int j = 0; j < 2; j++) {
            cp16(s + so + j * 16,          pAh + go + j * 8);
            cp16(s + ABYTES + so + j * 16, pBh + go + j * 8);
        }
        asm volatile("cp.async.commit_group;" ::: "memory");
    };

    float acc[2][8][4];
#pragma unroll
    for (int i = 0; i < 2; i++)
#pragma unroll
        for (int j = 0; j < 8; j++)
#pragma unroll
            for (int t = 0; t < 4; t++) acc[i][j][t] = 0.0f;

    const uint32_t aRowOff = (uint32_t)(wm * 32 + (lane & 15)) * LDB
                           + (uint32_t)(lane >> 4) * 16;
    const uint32_t bRowOff = (uint32_t)(wn * 64 + ((lane >> 4) * 8) + (lane & 7)) * LDB
                           + (uint32_t)((lane >> 3) & 1) * 16;

    load_tile(0, 0);
    load_tile(1, 1);
    int buf = 0;

    for (int kt = 0; kt < KTILES; kt++) {
        if (kt + 1 < KTILES) asm volatile("cp.async.wait_group 1;" ::: "memory");
        else                 asm volatile("cp.async.wait_group 0;" ::: "memory");
        __syncthreads();
        if (kt + 2 < KTILES) {
            int nbuf = buf + 2; if (nbuf >= 3) nbuf -= 3;
            load_tile(kt + 2, nbuf);
        }

        const uint32_t aHi = sb + buf * STAGE1;
        const uint32_t bHi = aHi + ABYTES;

#pragma unroll
        for (int ks = 0; ks < 2; ks++) {
            const uint32_t kso = (uint32_t)ks * 32;
            uint32_t ah[2][4];
#pragma unroll
            for (int mf = 0; mf < 2; mf++)
                ldm4(ah[mf], aHi + aRowOff + (uint32_t)mf * 16 * LDB + kso);
#pragma unroll
            for (int nfp = 0; nfp < 4; nfp++) {
                uint32_t bh[4];
                ldm4(bh, bHi + bRowOff + (uint32_t)nfp * 16 * LDB + kso);
#pragma unroll
                for (int p = 0; p < 2; p++) {
                    const int nf = nfp * 2 + p;
#pragma unroll
                    for (int mf = 0; mf < 2; mf++)
                        mmah(acc[mf][nf], ah[mf], bh[2 * p], bh[2 * p + 1]);
                }
            }
        }
        buf++; if (buf >= 3) buf -= 3;
    }

    const int mBase = mb * 128 + wm * 32 + (lane >> 2);
    const int nBase = nb * 128 + wn * 64 + (lane & 3) * 2;
#pragma unroll
    for (int mf = 0; mf < 2; mf++) {
#pragma unroll
        for (int nf = 0; nf < 8; nf++) {
            const int m = mBase + mf * 16;
            const int n = nBase + nf * 8;
            const float2 bb = *(const float2*)(bias + n);
            *(__half2*)(outH + (size_t)m * 2048 + n) = __halves2half2(
                __float2half_rn(acc[mf][nf][0] + bb.x),
                __float2half_rn(acc[mf][nf][1] + bb.y));
            *(__half2*)(outH + (size_t)(m + 8) * 2048 + n) = __halves2half2(
                __float2half_rn(acc[mf][nf][2] + bb.x),
                __float2half_rn(acc[mf][nf][3] + bb.y));
        }
    }
}

// ---------------------------------------------------------------------------
// 2-term fp16 GEMM-NT + bias (output projection): out = Ah*Bh + Al*Bh + bias,
// fp32 out. 3-stage pipeline, 2 CTAs/SM.
// ---------------------------------------------------------------------------
#define STAGE2  (3 * ABYTES)         // 30720 (Ah|Al|Bh)
#define GEMM2_SMEM (3 * STAGE2)      // 92160

__global__ __launch_bounds__(256, 2)
void gemm2_kernel(const __half* __restrict__ Ah, const __half* __restrict__ Al,
                  const __half* __restrict__ Bh, const float* __restrict__ bias,
                  float* __restrict__ out)
{
    extern __shared__ char smem[];
    const uint32_t sb = smem_u32(smem);
    const int tid  = threadIdx.x;
    const int wid  = tid >> 5;
    const int lane = tid & 31;
    const int nb = blockIdx.x, mb = blockIdx.y;
    const int wm = wid >> 1, wn = wid & 1;

    const __half* pAh = Ah + (size_t)(mb * 128) * 2048;
    const __half* pAl = Al + (size_t)(mb * 128) * 2048;
    const __half* pBh = Bh + (size_t)(nb * 128) * 2048;

    const int lr = tid >> 1;
    const int lc = (tid & 1) * 2;

    auto load_tile = [&](int kt, int buf) {
        const uint32_t s = sb + buf * STAGE2;
        const size_t go = (size_t)lr * 2048 + (size_t)kt * 32 + (size_t)lc * 8;
        const uint32_t so = (uint32_t)lr * LDB + (uint32_t)lc * 16;
#pragma unroll
        for (int j = 0; j < 2; j++) {
            cp16(s + so + j * 16,              pAh + go + j * 8);
            cp16(s + ABYTES     + so + j * 16, pAl + go + j * 8);
            cp16(s + 2 * ABYTES + so + j * 16, pBh + go + j * 8);
        }
        asm volatile("cp.async.commit_group;" ::: "memory");
    };

    float acc[2][8][4];
#pragma unroll
    for (int i = 0; i < 2; i++)
#pragma unroll
        for (int j = 0; j < 8; j++)
#pragma unroll
            for (int t = 0; t < 4; t++) acc[i][j][t] = 0.0f;

    const uint32_t aRowOff = (uint32_t)(wm * 32 + (lane & 15)) * LDB
                           + (uint32_t)(lane >> 4) * 16;
    const uint32_t bRowOff = (uint32_t)(wn * 64 + ((lane >> 4) * 8) + (lane & 7)) * LDB
                           + (uint32_t)((lane >> 3) & 1) * 16;

    load_tile(0, 0);
    load_tile(1, 1);
    int buf = 0;

    for (int kt = 0; kt < KTILES; kt++) {
        if (kt + 1 < KTILES) asm volatile("cp.async.wait_group 1;" ::: "memory");
        else                 asm volatile("cp.async.wait_group 0;" ::: "memory");
        __syncthreads();
        if (kt + 2 < KTILES) {
            int nbuf = buf + 2; if (nbuf >= 3) nbuf -= 3;
            load_tile(kt + 2, nbuf);
        }

        const uint32_t aHi = sb + buf * STAGE2;
        const uint32_t aLo = aHi + ABYTES;
        const uint32_t bHi = aHi + 2 * ABYTES;

#pragma unroll
        for (int ks = 0; ks < 2; ks++) {
            const uint32_t kso = (uint32_t)ks * 32;
            uint32_t ah[2][4], al[2][4];
#pragma unroll
            for (int mf = 0; mf < 2; mf++) {
                ldm4(ah[mf], aHi + aRowOff + (uint32_t)mf * 16 * LDB + kso);
                ldm4(al[mf], aLo + aRowOff + (uint32_t)mf * 16 * LDB + kso);
            }
#pragma unroll
            for (int nfp = 0; nfp < 4; nfp++) {
                uint32_t bh[4];
                ldm4(bh, bHi + bRowOff + (uint32_t)nfp * 16 * LDB + kso);
#pragma unroll
                for (int p = 0; p < 2; p++) {
                    const int nf = nfp * 2 + p;
#pragma unroll
                    for (int mf = 0; mf < 2; mf++) {
                        mmah(acc[mf][nf], ah[mf], bh[2 * p], bh[2 * p + 1]);
                        mmah(acc[mf][nf], al[mf], bh[2 * p], bh[2 * p + 1]);
                    }
                }
            }
        }
        buf++; if (buf >= 3) buf -= 3;
    }

    const int mBase = mb * 128 + wm * 32 + (lane >> 2);
    const int nBase = nb * 128 + wn * 64 + (lane & 3) * 2;
#pragma unroll
    for (int mf = 0; mf < 2; mf++) {
#pragma unroll
        for (int nf = 0; nf < 8; nf++) {
            const int m = mBase + mf * 16;
            const int n = nBase + nf * 8;
            const float2 bb = *(const float2*)(bias + n);
            *(float2*)(out + (size_t)m * 2048 + n) =
                make_float2(acc[mf][nf][0] + bb.x, acc[mf][nf][1] + bb.y);
            *(float2*)(out + (size_t)(m + 8) * 2048 + n) =
                make_float2(acc[mf][nf][2] + bb.x, acc[mf][nf][3] + bb.y);
        }
    }
}

// ---------------------------------------------------------------------------
// fp16 tensor-core flash attention + fused DP noise.
// 1-term QK^T; P fp16 in place; O += P*V (ldm.trans). ctx hi/lo fp16 out.
// ---------------------------------------------------------------------------
#define ALD      272
#define QH_OFF   0
#define KV_OFF   34816
#define KV_STAGE 34816
#define KH_O     0
#define V_O      17408
#define SP_OFF   104448
#define MS_OFF   139264
#define LS_OFF   139776
#define AL_OFF   140288
#define ATTN_SMEM 140800

__global__ __launch_bounds__(256, 1)
void attn_mma_kernel(const __half* __restrict__ Qh, const __half* __restrict__ Kh,
                     const __half* __restrict__ Vh, const float* __restrict__ Ng,
                     __half* __restrict__ Ohi, __half* __restrict__ Olo)
{
    extern __shared__ char smem[];
    const uint32_t sb = smem_u32(smem);
    const int tid  = threadIdx.x;
    const int wid  = tid >> 5;
    const int lane = tid & 31;
    const int wm = wid >> 1, wn = wid & 1;

    const int b  = blockIdx.z;
    const int h  = blockIdx.y;
    const int q0 = blockIdx.x * 128;

    const size_t rowg0 = (size_t)b * S_ + q0;
    const size_t brow0 = (size_t)b * S_;
    const size_t hoff  = (size_t)h * D_;

    float* m_s  = (float*)(smem + MS_OFF);
    float* l_s  = (float*)(smem + LS_OFF);
    float* al_s = (float*)(smem + AL_OFF);

    // ---- load Q ----
    {
        const int r  = tid >> 1;
        const int cb = (tid & 1) * 8;
        const __half* gqh = Qh + (rowg0 + r) * E_ + hoff + cb * 8;
        const uint32_t sq = (uint32_t)r * ALD + (uint32_t)cb * 16;
#pragma unroll
        for (int j = 0; j < 8; j++)
            cp16(sb + QH_OFF + sq + j * 16, gqh + j * 8);
        asm volatile("cp.async.commit_group;" ::: "memory");
    }
    if (tid < 128) { m_s[tid] = -INFINITY; l_s[tid] = 0.0f; }

    const int kr  = tid >> 2;
    const int kcb = (tid & 3) * 4;
    auto kvload = [&](int t, int buf) {
        const uint32_t s = sb + KV_OFF + buf * KV_STAGE;
        const size_t grow = (brow0 + t * 64 + kr) * E_ + hoff + kcb * 8;
        const uint32_t so = (uint32_t)kr * ALD + (uint32_t)kcb * 16;
#pragma unroll
        for (int j = 0; j < 4; j++) {
            cp16(s + KH_O + so + j * 16, Kh + grow + j * 8);
            cp16(s + V_O  + so + j * 16, Vh + grow + j * 8);
        }
        asm volatile("cp.async.commit_group;" ::: "memory");
    };

    float acc_o[2][8][4];
#pragma unroll
    for (int i = 0; i < 2; i++)
#pragma unroll
        for (int j = 0; j < 8; j++)
#pragma unroll
            for (int t = 0; t < 4; t++) acc_o[i][j][t] = 0.0f;

    const uint32_t aRowOff = (uint32_t)(wm * 32 + (lane & 15)) * ALD
                           + (uint32_t)(lane >> 4) * 16;
    const uint32_t bRowOffS = (uint32_t)(wn * 32 + ((lane >> 4) * 8) + (lane & 7)) * ALD
                            + (uint32_t)((lane >> 3) & 1) * 16;
    const uint32_t vRowOff = (uint32_t)(lane & 15) * ALD + (uint32_t)(lane >> 4) * 16;

    kvload(0, 0);

    for (int t = 0; t < S_ / 64; t++) {
        const int buf = t & 1;
        if (t + 1 < S_ / 64) {
            kvload(t + 1, buf ^ 1);
            asm volatile("cp.async.wait_group 1;" ::: "memory");
        } else {
            asm volatile("cp.async.wait_group 0;" ::: "memory");
        }
        __syncthreads();

        const uint32_t kHi   = sb + KV_OFF + buf * KV_STAGE + KH_O;
        const uint32_t vBase = sb + KV_OFF + buf * KV_STAGE + V_O;

        // ---- S = Q K^T (1-term fp16) ----
        float acc_s[2][4][4];
#pragma unroll
        for (int i = 0; i < 2; i++)
#pragma unroll
            for (int j = 0; j < 4; j++)
#pragma unroll
                for (int q = 0; q < 4; q++) acc_s[i][j][q] = 0.0f;

#pragma unroll
        for (int ks = 0; ks < 8; ks++) {
            const uint32_t kso = (uint32_t)ks * 32;
            uint32_t ah[2][4];
#pragma unroll
            for (int mf = 0; mf < 2; mf++)
                ldm4(ah[mf], sb + QH_OFF + aRowOff + (uint32_t)mf * 16 * ALD + kso);
#pragma unroll
            for (int nfp = 0; nfp < 2; nfp++) {
                uint32_t bh[4];
                ldm4(bh, kHi + bRowOffS + (uint32_t)nfp * 16 * ALD + kso);
#pragma unroll
                for (int p = 0; p < 2; p++) {
                    const int nf = nfp * 2 + p;
#pragma unroll
                    for (int mf = 0; mf < 2; mf++)
                        mmah(acc_s[mf][nf], ah[mf], bh[2 * p], bh[2 * p + 1]);
                }
            }
        }

        // ---- store S (scaled) to smem fp32 ----
#pragma unroll
        for (int mf = 0; mf < 2; mf++) {
#pragma unroll
            for (int nf = 0; nf < 4; nf++) {
                const int r = wm * 32 + mf * 16 + (lane >> 2);
                const int c = wn * 32 + nf * 8 + (lane & 3) * 2;
                *(float2*)(smem + SP_OFF + (size_t)r * ALD + c * 4) =
                    make_float2(acc_s[mf][nf][0] * ATTN_SCALE,
                                acc_s[mf][nf][1] * ATTN_SCALE);
                *(float2*)(smem + SP_OFF + (size_t)(r + 8) * ALD + c * 4) =
                    make_float2(acc_s[mf][nf][2] * ATTN_SCALE,
                                acc_s[mf][nf][3] * ATTN_SCALE);
            }
        }
        __syncthreads();

        // ---- online softmax; P fp16 in place ----
#pragma unroll
        for (int rr = 0; rr < 16; rr++) {
            const int row = wid * 16 + rr;
            char* prow = smem + SP_OFF + (size_t)row * ALD;
            float s0 = ((float*)prow)[lane];
            float s1 = ((float*)prow)[32 + lane];
            float mx = fmaxf(s0, s1);
#pragma unroll
            for (int off = 16; off; off >>= 1)
                mx = fmaxf(mx, __shfl_xor_sync(0xffffffffu, mx, off));
            const float m_old = m_s[row];
            const float m_new = fmaxf(m_old, mx);
            const float p0 = __expf(s0 - m_new);
            const float p1 = __expf(s1 - m_new);
            float sum = p0 + p1;
#pragma unroll
            for (int off = 16; off; off >>= 1)
                sum += __shfl_xor_sync(0xffffffffu, sum, off);
            ((__half*)prow)[lane]      = __float2half_rn(p0);
            ((__half*)prow)[32 + lane] = __float2half_rn(p1);
            if (lane == 0) {
                const float alpha = __expf(m_old - m_new);
                m_s[row] = m_new;
                l_s[row] = l_s[row] * alpha + sum;
                al_s[row] = alpha;
            }
        }
        __syncthreads();

        // ---- rescale O ----
#pragma unroll
        for (int mf = 0; mf < 2; mf++) {
            const int rbase = wm * 32 + mf * 16 + (lane >> 2);
            const float a0 = al_s[rbase];
            const float a1 = al_s[rbase + 8];
#pragma unroll
            for (int nf = 0; nf < 8; nf++) {
                acc_o[mf][nf][0] *= a0; acc_o[mf][nf][1] *= a0;
                acc_o[mf][nf][2] *= a1; acc_o[mf][nf][3] *= a1;
            }
        }

        // ---- O += P @ V ----
#pragma unroll
        for (int ks2 = 0; ks2 < 4; ks2++) {
            uint32_t pa[2][4];
#pragma unroll
            for (int mf = 0; mf < 2; mf++)
                ldm4(pa[mf], sb + SP_OFF + aRowOff + (uint32_t)mf * 16 * ALD
                           + (uint32_t)ks2 * 32);
#pragma unroll
            for (int nfp = 0; nfp < 4; nfp++) {
                uint32_t vr[4];
                ldm4t(vr, vBase + vRowOff + (uint32_t)ks2 * 16 * ALD
                        + (uint32_t)(wn * 64 + nfp * 16) * 2);
#pragma unroll
                for (int mf = 0; mf < 2; mf++) {
                    mmah(acc_o[mf][nfp * 2],     pa[mf], vr[0], vr[1]);
                    mmah(acc_o[mf][nfp * 2 + 1], pa[mf], vr[2], vr[3]);
                }
            }
        }
    }

    // ---- epilogue: normalize, DP noise, split fp16 hi/lo ----
#pragma unroll
    for (int mf = 0; mf < 2; mf++) {
        const int rbase = wm * 32 + mf * 16 + (lane >> 2);
        const float inv0 = 1.0f / l_s[rbase];
        const float inv1 = 1.0f / l_s[rbase + 8];
#pragma unroll
        for (int nf = 0; nf < 8; nf++) {
            const int n = wn * 64 + nf * 8 + (lane & 3) * 2;
            const size_t g0 = (rowg0 + rbase) * E_ + hoff + n;
            const size_t g1 = (rowg0 + rbase + 8) * E_ + hoff + n;
            float2 n0 = *(const float2*)(Ng + g0);
            float2 n1 = *(const float2*)(Ng + g1);
            float v00 = acc_o[mf][nf][0] * inv0 + NSCALE * n0.x;
            float v01 = acc_o[mf][nf][1] * inv0 + NSCALE * n0.y;
            float v10 = acc_o[mf][nf][2] * inv1 + NSCALE * n1.x;
            float v11 = acc_o[mf][nf][3] * inv1 + NSCALE * n1.y;
            __half h00 = __float2half_rn(v00), h01 = __float2half_rn(v01);
            __half h10 = __float2half_rn(v10), h11 = __float2half_rn(v11);
            *(__half2*)(Ohi + g0) = __halves2half2(h00, h01);
            *(__half2*)(Ohi + g1) = __halves2half2(h10, h11);
            *(__half2*)(Olo + g0) = __halves2half2(
                __float2half_rn(v00 - __half2float(h00)),
                __float2half_rn(v01 - __half2float(h01)));
            *(__half2*)(Olo + g1) = __halves2half2(
                __float2half_rn(v10 - __half2float(h10)),
                __float2half_rn(v11 - __half2float(h11)));
        }
    }
}

// ---------------------------------------------------------------------------
// Launch
// ---------------------------------------------------------------------------
extern "C" void kernel_launch(void* const* d_in, const int* in_sizes, int n_in,
                              void* d_out, int out_size)
{
    const float* query = (const float*)d_in[0];
    const float* key_t = (const float*)d_in[1];
    const float* value = (const float*)d_in[2];
    const float* Wq    = (const float*)d_in[3];
    const float* bq    = (const float*)d_in[4];
    const float* Wk    = (const float*)d_in[5];
    const float* bk    = (const float*)d_in[6];
    const float* Wv    = (const float*)d_in[7];
    const float* bv    = (const float*)d_in[8];
    const float* Wo    = (const float*)d_in[9];
    const float* bo    = (const float*)d_in[10];
    const float* noise = (const float*)d_in[11];
    float* out = (float*)d_out;

    __half *xh, *wh, *qh, *kh, *vh, *ch, *cl;
    cudaGetSymbolAddress((void**)&xh, g_xh);
    cudaGetSymbolAddress((void**)&wh, g_wh);
    cudaGetSymbolAddress((void**)&qh, g_qh);
    cudaGetSymbolAddress((void**)&kh, g_kh);
    cudaGetSymbolAddress((void**)&vh, g_vh);
    cudaGetSymbolAddress((void**)&ch, g_ch);
    cudaGetSymbolAddress((void**)&cl, g_cl);

    cudaFuncSetAttribute(gemm1_kernel,
                         cudaFuncAttributeMaxDynamicSharedMemorySize, GEMM1_SMEM);
    cudaFuncSetAttribute(gemm2_kernel,
                         cudaFuncAttributeMaxDynamicSharedMemorySize, GEMM2_SMEM);
    cudaFuncSetAttribute(attn_mma_kernel,
                         cudaFuncAttributeMaxDynamicSharedMemorySize, ATTN_SMEM);

    const size_t xTot = (size_t)MTOT * E_;
    const size_t wTot = (size_t)E_ * E_;
    const int cX = (int)((xTot / 8 + 255) / 256);
    const int cW = (int)((wTot / 8 + 255) / 256);
    dim3 gemmGrid(E_ / 128, MTOT / 128);   // (16, 64)

    // Q = query @ Wq^T + bq
    convert_h<<<cX, 256>>>(query, xh, xTot);
    convert_h<<<cW, 256>>>(Wq, wh, wTot);
    gemm1_kernel<<<gemmGrid, 256, GEMM1_SMEM>>>(xh, wh, bq, qh);

    // K = key_t @ Wk^T + bk
    convert_h<<<cX, 256>>>(key_t, xh, xTot);
    convert_h<<<cW, 256>>>(Wk, wh, wTot);
    gemm1_kernel<<<gemmGrid, 256, GEMM1_SMEM>>>(xh, wh, bk, kh);

    // V = value @ Wv^T + bv
    convert_h<<<cX, 256>>>(value, xh, xTot);
    convert_h<<<cW, 256>>>(Wv, wh, wTot);
    gemm1_kernel<<<gemmGrid, 256, GEMM1_SMEM>>>(xh, wh, bv, vh);

    // Attention + DP noise -> ctx hi/lo
    dim3 attnGrid(S_ / 128, H_, B_);       // (16, 16, 4)
    attn_mma_kernel<<<attnGrid, 256, ATTN_SMEM>>>(qh, kh, vh, noise, ch, cl);

    // out = ctx @ Wo^T + bo  (2-term: ctx exact, Wo rounded)
    convert_h<<<cW, 256>>>(Wo, wh, wTot);
    gemm2_kernel<<<gemmGrid, 256, GEMM2_SMEM>>>(ch, cl, wh, bo, out);
}

// round 9
// speedup vs baseline: 5.2402x; 1.4485x over previous
#include <cuda_runtime.h>
#include <cuda_fp16.h>
#include <math.h>
#include <stdint.h>

// ---------------------------------------------------------------------------
// Problem constants
// ---------------------------------------------------------------------------
#define B_   4
#define S_   2048
#define E_   2048
#define H_   16
#define D_   128
#define MTOT (B_ * S_)

#define NSCALE 4.84480515f                 // sqrt(2*ln(1.25/1e-5))
#define ATTN_SCALE 0.08838834764831845f    // 1/sqrt(128)

// ---------------------------------------------------------------------------
// Scratch (__device__ globals)
// ---------------------------------------------------------------------------
__device__ __half g_xh[(size_t)MTOT * E_];
__device__ __half g_wh[(size_t)E_ * E_];
__device__ __half g_qh[(size_t)MTOT * E_];
__device__ __half g_kh[(size_t)MTOT * E_];
__device__ __half g_vh[(size_t)MTOT * E_];
__device__ __half g_ch[(size_t)MTOT * E_];
__device__ __half g_cl[(size_t)MTOT * E_];

// ---------------------------------------------------------------------------
// PTX helpers
// ---------------------------------------------------------------------------
__device__ __forceinline__ uint32_t smem_u32(const void* p) {
    uint32_t a;
    asm("{ .reg .u64 t; cvta.to.shared.u64 t, %1; cvt.u32.u64 %0, t; }"
        : "=r"(a) : "l"(p));
    return a;
}

__device__ __forceinline__ void cp16(uint32_t dst, const void* src) {
    asm volatile("cp.async.cg.shared.global [%0], [%1], 16;"
                 :: "r"(dst), "l"(src) : "memory");
}

__device__ __forceinline__ void ldm4(uint32_t* r, uint32_t addr) {
    asm volatile("ldmatrix.sync.aligned.m8n8.x4.shared.b16 {%0,%1,%2,%3}, [%4];"
                 : "=r"(r[0]), "=r"(r[1]), "=r"(r[2]), "=r"(r[3])
                 : "r"(addr));
}

__device__ __forceinline__ void ldm4t(uint32_t* r, uint32_t addr) {
    asm volatile("ldmatrix.sync.aligned.m8n8.x4.trans.shared.b16 {%0,%1,%2,%3}, [%4];"
                 : "=r"(r[0]), "=r"(r[1]), "=r"(r[2]), "=r"(r[3])
                 : "r"(addr));
}

__device__ __forceinline__ void mmah(float* c, const uint32_t* a,
                                     uint32_t b0, uint32_t b1) {
    asm volatile(
        "mma.sync.aligned.m16n8k16.row.col.f32.f16.f16.f32 "
        "{%0,%1,%2,%3}, {%4,%5,%6,%7}, {%8,%9}, {%0,%1,%2,%3};"
        : "+f"(c[0]), "+f"(c[1]), "+f"(c[2]), "+f"(c[3])
        : "r"(a[0]), "r"(a[1]), "r"(a[2]), "r"(a[3]), "r"(b0), "r"(b1));
}

// ---------------------------------------------------------------------------
// Convert: fp32 -> fp16
// ---------------------------------------------------------------------------
__global__ void convert_h(const float* __restrict__ in,
                          __half* __restrict__ hi, size_t total)
{
    size_t idx = ((size_t)blockIdx.x * blockDim.x + threadIdx.x) * 8;
    if (idx >= total) return;
    float4 a = *(const float4*)(in + idx);
    float4 b = *(const float4*)(in + idx + 4);
    float v[8] = {a.x, a.y, a.z, a.w, b.x, b.y, b.z, b.w};
    __half h8[8];
#pragma unroll
    for (int i = 0; i < 8; i++) h8[i] = __float2half_rn(v[i]);
    *(uint4*)(hi + idx) = *(uint4*)h8;
}

// ---------------------------------------------------------------------------
// 1-term fp16 GEMM-NT + bias (QKV projections). Unchanged from R7.
// ---------------------------------------------------------------------------
#define LDB     80
#define ABYTES  (128 * LDB)
#define STAGE1  (2 * ABYTES)
#define GEMM1_SMEM (3 * STAGE1)
#define KTILES  64

__global__ __launch_bounds__(256, 2)
void gemm1_kernel(const __half* __restrict__ Ah, const __half* __restrict__ Bh,
                  const float* __restrict__ bias, __half* __restrict__ outH)
{
    extern __shared__ char smem[];
    const uint32_t sb = smem_u32(smem);
    const int tid  = threadIdx.x;
    const int wid  = tid >> 5;
    const int lane = tid & 31;
    const int nb = blockIdx.x, mb = blockIdx.y;
    const int wm = wid >> 1, wn = wid & 1;

    const __half* pAh = Ah + (size_t)(mb * 128) * 2048;
    const __half* pBh = Bh + (size_t)(nb * 128) * 2048;

    const int lr = tid >> 1;
    const int lc = (tid & 1) * 2;

    auto load_tile = [&](int kt, int buf) {
        const uint32_t s = sb + buf * STAGE1;
        const size_t go = (size_t)lr * 2048 + (size_t)kt * 32 + (size_t)lc * 8;
        const uint32_t so = (uint32_t)lr * LDB + (uint32_t)lc * 16;
#pragma unroll
        for (int j = 0; j < 2; j++) {
            cp16(s + so + j * 16,          pAh + go + j * 8);
            cp16(s + ABYTES + so + j * 16, pBh + go + j * 8);
        }
        asm volatile("cp.async.commit_group;" ::: "memory");
    };

    float acc[2][8][4];
#pragma unroll
    for (int i = 0; i < 2; i++)
#pragma unroll
        for (int j = 0; j < 8; j++)
#pragma unroll
            for (int t = 0; t < 4; t++) acc[i][j][t] = 0.0f;

    const uint32_t aRowOff = (uint32_t)(wm * 32 + (lane & 15)) * LDB
                           + (uint32_t)(lane >> 4) * 16;
    const uint32_t bRowOff = (uint32_t)(wn * 64 + ((lane >> 4) * 8) + (lane & 7)) * LDB
                           + (uint32_t)((lane >> 3) & 1) * 16;

    load_tile(0, 0);
    load_tile(1, 1);
    int buf = 0;

    for (int kt = 0; kt < KTILES; kt++) {
        if (kt + 1 < KTILES) asm volatile("cp.async.wait_group 1;" ::: "memory");
        else                 asm volatile("cp.async.wait_group 0;" ::: "memory");
        __syncthreads();
        if (kt + 2 < KTILES) {
            int nbuf = buf + 2; if (nbuf >= 3) nbuf -= 3;
            load_tile(kt + 2, nbuf);
        }

        const uint32_t aHi = sb + buf * STAGE1;
        const uint32_t bHi = aHi + ABYTES;

#pragma unroll
        for (int ks = 0; ks < 2; ks++) {
            const uint32_t kso = (uint32_t)ks * 32;
            uint32_t ah[2][4];
#pragma unroll
            for (int mf = 0; mf < 2; mf++)
                ldm4(ah[mf], aHi + aRowOff + (uint32_t)mf * 16 * LDB + kso);
#pragma unroll
            for (int nfp = 0; nfp < 4; nfp++) {
                uint32_t bh[4];
                ldm4(bh, bHi + bRowOff + (uint32_t)nfp * 16 * LDB + kso);
#pragma unroll
                for (int p = 0; p < 2; p++) {
                    const int nf = nfp * 2 + p;
#pragma unroll
                    for (int mf = 0; mf < 2; mf++)
                        mmah(acc[mf][nf], ah[mf], bh[2 * p], bh[2 * p + 1]);
                }
            }
        }
        buf++; if (buf >= 3) buf -= 3;
    }

    const int mBase = mb * 128 + wm * 32 + (lane >> 2);
    const int nBase = nb * 128 + wn * 64 + (lane & 3) * 2;
#pragma unroll
    for (int mf = 0; mf < 2; mf++) {
#pragma unroll
        for (int nf = 0; nf < 8; nf++) {
            const int m = mBase + mf * 16;
            const int n = nBase + nf * 8;
            const float2 bb = *(const float2*)(bias + n);
            *(__half2*)(outH + (size_t)m * 2048 + n) = __halves2half2(
                __float2half_rn(acc[mf][nf][0] + bb.x),
                __float2half_rn(acc[mf][nf][1] + bb.y));
            *(__half2*)(outH + (size_t)(m + 8) * 2048 + n) = __halves2half2(
                __float2half_rn(acc[mf][nf][2] + bb.x),
                __float2half_rn(acc[mf][nf][3] + bb.y));
        }
    }
}

// ---------------------------------------------------------------------------
// 2-term fp16 GEMM-NT + bias (output projection). Unchanged from R7.
// ---------------------------------------------------------------------------
#define STAGE2  (3 * ABYTES)
#define GEMM2_SMEM (3 * STAGE2)

__global__ __launch_bounds__(256, 2)
void gemm2_kernel(const __half* __restrict__ Ah, const __half* __restrict__ Al,
                  const __half* __restrict__ Bh, const float* __restrict__ bias,
                  float* __restrict__ out)
{
    extern __shared__ char smem[];
    const uint32_t sb = smem_u32(smem);
    const int tid  = threadIdx.x;
    const int wid  = tid >> 5;
    const int lane = tid & 31;
    const int nb = blockIdx.x, mb = blockIdx.y;
    const int wm = wid >> 1, wn = wid & 1;

    const __half* pAh = Ah + (size_t)(mb * 128) * 2048;
    const __half* pAl = Al + (size_t)(mb * 128) * 2048;
    const __half* pBh = Bh + (size_t)(nb * 128) * 2048;

    const int lr = tid >> 1;
    const int lc = (tid & 1) * 2;

    auto load_tile = [&](int kt, int buf) {
        const uint32_t s = sb + buf * STAGE2;
        const size_t go = (size_t)lr * 2048 + (size_t)kt * 32 + (size_t)lc * 8;
        const uint32_t so = (uint32_t)lr * LDB + (uint32_t)lc * 16;
#pragma unroll
        for (int j = 0; j < 2; j++) {
            cp16(s + so + j * 16,              pAh + go + j * 8);
            cp16(s + ABYTES     + so + j * 16, pAl + go + j * 8);
            cp16(s + 2 * ABYTES + so + j * 16, pBh + go + j * 8);
        }
        asm volatile("cp.async.commit_group;" ::: "memory");
    };

    float acc[2][8][4];
#pragma unroll
    for (int i = 0; i < 2; i++)
#pragma unroll
        for (int j = 0; j < 8; j++)
#pragma unroll
            for (int t = 0; t < 4; t++) acc[i][j][t] = 0.0f;

    const uint32_t aRowOff = (uint32_t)(wm * 32 + (lane & 15)) * LDB
                           + (uint32_t)(lane >> 4) * 16;
    const uint32_t bRowOff = (uint32_t)(wn * 64 + ((lane >> 4) * 8) + (lane & 7)) * LDB
                           + (uint32_t)((lane >> 3) & 1) * 16;

    load_tile(0, 0);
    load_tile(1, 1);
    int buf = 0;

    for (int kt = 0; kt < KTILES; kt++) {
        if (kt + 1 < KTILES) asm volatile("cp.async.wait_group 1;" ::: "memory");
        else                 asm volatile("cp.async.wait_group 0;" ::: "memory");
        __syncthreads();
        if (kt + 2 < KTILES) {
            int nbuf = buf + 2; if (nbuf >= 3) nbuf -= 3;
            load_tile(kt + 2, nbuf);
        }

        const uint32_t aHi = sb + buf * STAGE2;
        const uint32_t aLo = aHi + ABYTES;
        const uint32_t bHi = aHi + 2 * ABYTES;

#pragma unroll
        for (int ks = 0; ks < 2; ks++) {
            const uint32_t kso = (uint32_t)ks * 32;
            uint32_t ah[2][4], al[2][4];
#pragma unroll
            for (int mf = 0; mf < 2; mf++) {
                ldm4(ah[mf], aHi + aRowOff + (uint32_t)mf * 16 * LDB + kso);
                ldm4(al[mf], aLo + aRowOff + (uint32_t)mf * 16 * LDB + kso);
            }
#pragma unroll
            for (int nfp = 0; nfp < 4; nfp++) {
                uint32_t bh[4];
                ldm4(bh, bHi + bRowOff + (uint32_t)nfp * 16 * LDB + kso);
#pragma unroll
                for (int p = 0; p < 2; p++) {
                    const int nf = nfp * 2 + p;
#pragma unroll
                    for (int mf = 0; mf < 2; mf++) {
                        mmah(acc[mf][nf], ah[mf], bh[2 * p], bh[2 * p + 1]);
                        mmah(acc[mf][nf], al[mf], bh[2 * p], bh[2 * p + 1]);
                    }
                }
            }
        }
        buf++; if (buf >= 3) buf -= 3;
    }

    const int mBase = mb * 128 + wm * 32 + (lane >> 2);
    const int nBase = nb * 128 + wn * 64 + (lane & 3) * 2;
#pragma unroll
    for (int mf = 0; mf < 2; mf++) {
#pragma unroll
        for (int nf = 0; nf < 8; nf++) {
            const int m = mBase + mf * 16;
            const int n = nBase + nf * 8;
            const float2 bb = *(const float2*)(bias + n);
            *(float2*)(out + (size_t)m * 2048 + n) =
                make_float2(acc[mf][nf][0] + bb.x, acc[mf][nf][1] + bb.y);
            *(float2*)(out + (size_t)(m + 8) * 2048 + n) =
                make_float2(acc[mf][nf][2] + bb.x, acc[mf][nf][3] + bb.y);
        }
    }
}

// ---------------------------------------------------------------------------
// fp16 flash attention, fully register-resident softmax (FA2-style).
// 8 warps; warp w owns q-rows [w*16, w*16+16) x all 64 kv cols.
// S c-frags -> warp-local shfl softmax -> P a-frags packed in registers ->
// O += P x V. No S/P smem, 2 barriers/tile. ctx hi/lo fp16 + DP noise out.
// ---------------------------------------------------------------------------
#define ALD      272
#define QH_OFF   0
#define KV_OFF   34816
#define KV_STAGE 34816
#define V_O      17408
#define ATTN_SMEM 104448

__global__ __launch_bounds__(256, 1)
void attn_mma_kernel(const __half* __restrict__ Qh, const __half* __restrict__ Kh,
                     const __half* __restrict__ Vh, const float* __restrict__ Ng,
                     __half* __restrict__ Ohi, __half* __restrict__ Olo)
{
    extern __shared__ char smem[];
    const uint32_t sb = smem_u32(smem);
    const int tid  = threadIdx.x;
    const int wid  = tid >> 5;
    const int lane = tid & 31;

    const int b  = blockIdx.z;
    const int h  = blockIdx.y;
    const int q0 = blockIdx.x * 128;

    const size_t rowg0 = (size_t)b * S_ + q0;
    const size_t brow0 = (size_t)b * S_;
    const size_t hoff  = (size_t)h * D_;

    // ---- load Q tile ----
    {
        const int r  = tid >> 1;
        const int cb = (tid & 1) * 8;
        const __half* gqh = Qh + (rowg0 + r) * E_ + hoff + cb * 8;
        const uint32_t sq = (uint32_t)r * ALD + (uint32_t)cb * 16;
#pragma unroll
        for (int j = 0; j < 8; j++)
            cp16(sb + QH_OFF + sq + j * 16, gqh + j * 8);
        asm volatile("cp.async.commit_group;" ::: "memory");
    }

    const int kr  = tid >> 2;
    const int kcb = (tid & 3) * 4;
    auto kvload = [&](int t, int buf) {
        const uint32_t s = sb + KV_OFF + buf * KV_STAGE;
        const size_t grow = (brow0 + t * 64 + kr) * E_ + hoff + kcb * 8;
        const uint32_t so = (uint32_t)kr * ALD + (uint32_t)kcb * 16;
#pragma unroll
        for (int j = 0; j < 4; j++) {
            cp16(s + so + j * 16,       Kh + grow + j * 8);
            cp16(s + V_O + so + j * 16, Vh + grow + j * 8);
        }
        asm volatile("cp.async.commit_group;" ::: "memory");
    };

    // output accumulators: 16 q-rows x 128 d cols per warp = 16 n8 frags
    float acc_o[16][4];
#pragma unroll
    for (int j = 0; j < 16; j++)
#pragma unroll
        for (int t = 0; t < 4; t++) acc_o[j][t] = 0.0f;

    float m0 = -INFINITY, m1 = -INFINITY, l0 = 0.0f, l1 = 0.0f;

    // ldmatrix address components
    const uint32_t aRowOff = (uint32_t)(wid * 16 + (lane & 15)) * ALD
                           + (uint32_t)(lane >> 4) * 16;
    const uint32_t bRowOff = (uint32_t)(((lane >> 4) * 8) + (lane & 7)) * ALD
                           + (uint32_t)((lane >> 3) & 1) * 16;
    const uint32_t vRowOff = (uint32_t)(lane & 15) * ALD + (uint32_t)(lane >> 4) * 16;

    kvload(0, 0);

    for (int t = 0; t < S_ / 64; t++) {
        const int buf = t & 1;
        if (t + 1 < S_ / 64) {
            kvload(t + 1, buf ^ 1);
            asm volatile("cp.async.wait_group 1;" ::: "memory");
        } else {
            asm volatile("cp.async.wait_group 0;" ::: "memory");
        }
        __syncthreads();

        const uint32_t kBase = sb + KV_OFF + buf * KV_STAGE;
        const uint32_t vBase = kBase + V_O;

        // ---- S = Q K^T : warp computes 16 rows x 64 cols ----
        float s[8][4];
#pragma unroll
        for (int j = 0; j < 8; j++)
#pragma unroll
            for (int q = 0; q < 4; q++) s[j][q] = 0.0f;

#pragma unroll
        for (int ks = 0; ks < 8; ks++) {
            const uint32_t kso = (uint32_t)ks * 32;
            uint32_t ah[4];
            ldm4(ah, sb + QH_OFF + aRowOff + kso);
#pragma unroll
            for (int nfp = 0; nfp < 4; nfp++) {
                uint32_t bh[4];
                ldm4(bh, kBase + bRowOff + (uint32_t)nfp * 16 * ALD + kso);
                mmah(s[nfp * 2],     ah, bh[0], bh[1]);
                mmah(s[nfp * 2 + 1], ah, bh[2], bh[3]);
            }
        }

        // ---- register softmax (rows r0 = wid*16+(lane>>2), r1 = r0+8) ----
        float mx0 = -INFINITY, mx1 = -INFINITY;
#pragma unroll
        for (int j = 0; j < 8; j++) {
            s[j][0] *= ATTN_SCALE; s[j][1] *= ATTN_SCALE;
            s[j][2] *= ATTN_SCALE; s[j][3] *= ATTN_SCALE;
            mx0 = fmaxf(mx0, fmaxf(s[j][0], s[j][1]));
            mx1 = fmaxf(mx1, fmaxf(s[j][2], s[j][3]));
        }
        mx0 = fmaxf(mx0, __shfl_xor_sync(0xffffffffu, mx0, 1));
        mx0 = fmaxf(mx0, __shfl_xor_sync(0xffffffffu, mx0, 2));
        mx1 = fmaxf(mx1, __shfl_xor_sync(0xffffffffu, mx1, 1));
        mx1 = fmaxf(mx1, __shfl_xor_sync(0xffffffffu, mx1, 2));

        const float mn0 = fmaxf(m0, mx0);
        const float mn1 = fmaxf(m1, mx1);

        float sum0 = 0.0f, sum1 = 0.0f;
        uint32_t pf[4][4];                 // P a-frags per 16-kv chunk
#pragma unroll
        for (int j = 0; j < 8; j++) {
            s[j][0] = __expf(s[j][0] - mn0);
            s[j][1] = __expf(s[j][1] - mn0);
            s[j][2] = __expf(s[j][2] - mn1);
            s[j][3] = __expf(s[j][3] - mn1);
            sum0 += s[j][0] + s[j][1];
            sum1 += s[j][2] + s[j][3];
        }
#pragma unroll
        for (int k2 = 0; k2 < 4; k2++) {
            const int ja = k2 * 2, jb = k2 * 2 + 1;
            __half2 a0 = __floats2half2_rn(s[ja][0], s[ja][1]);
            __half2 a1 = __floats2half2_rn(s[ja][2], s[ja][3]);
            __half2 a2 = __floats2half2_rn(s[jb][0], s[jb][1]);
            __half2 a3 = __floats2half2_rn(s[jb][2], s[jb][3]);
            pf[k2][0] = *(uint32_t*)&a0;
            pf[k2][1] = *(uint32_t*)&a1;
            pf[k2][2] = *(uint32_t*)&a2;
            pf[k2][3] = *(uint32_t*)&a3;
        }
        sum0 += __shfl_xor_sync(0xffffffffu, sum0, 1);
        sum0 += __shfl_xor_sync(0xffffffffu, sum0, 2);
        sum1 += __shfl_xor_sync(0xffffffffu, sum1, 1);
        sum1 += __shfl_xor_sync(0xffffffffu, sum1, 2);

        const float alpha0 = __expf(m0 - mn0);
        const float alpha1 = __expf(m1 - mn1);
        m0 = mn0; m1 = mn1;
        l0 = l0 * alpha0 + sum0;
        l1 = l1 * alpha1 + sum1;

        // ---- rescale O ----
#pragma unroll
        for (int j = 0; j < 16; j++) {
            acc_o[j][0] *= alpha0; acc_o[j][1] *= alpha0;
            acc_o[j][2] *= alpha1; acc_o[j][3] *= alpha1;
        }

        // ---- O += P @ V ----
#pragma unroll
        for (int k2 = 0; k2 < 4; k2++) {
#pragma unroll
            for (int nfp = 0; nfp < 8; nfp++) {
                uint32_t vr[4];
                ldm4t(vr, vBase + vRowOff + (uint32_t)k2 * 16 * ALD
                        + (uint32_t)(nfp * 16) * 2);
                mmah(acc_o[nfp * 2],     pf[k2], vr[0], vr[1]);
                mmah(acc_o[nfp * 2 + 1], pf[k2], vr[2], vr[3]);
            }
        }
        __syncthreads();   // release KV buffer before next prefetch overwrites
    }

    // ---- epilogue: normalize, DP noise, split fp16 hi/lo ----
    const int r0 = wid * 16 + (lane >> 2);
    const float inv0 = 1.0f / l0;
    const float inv1 = 1.0f / l1;
#pragma unroll
    for (int nf = 0; nf < 16; nf++) {
        const int n = nf * 8 + (lane & 3) * 2;
        const size_t g0 = (rowg0 + r0) * E_ + hoff + n;
        const size_t g1 = (rowg0 + r0 + 8) * E_ + hoff + n;
        float2 n0 = *(const float2*)(Ng + g0);
        float2 n1 = *(const float2*)(Ng + g1);
        float v00 = acc_o[nf][0] * inv0 + NSCALE * n0.x;
        float v01 = acc_o[nf][1] * inv0 + NSCALE * n0.y;
        float v10 = acc_o[nf][2] * inv1 + NSCALE * n1.x;
        float v11 = acc_o[nf][3] * inv1 + NSCALE * n1.y;
        __half h00 = __float2half_rn(v00), h01 = __float2half_rn(v01);
        __half h10 = __float2half_rn(v10), h11 = __float2half_rn(v11);
        *(__half2*)(Ohi + g0) = __halves2half2(h00, h01);
        *(__half2*)(Ohi + g1) = __halves2half2(h10, h11);
        *(__half2*)(Olo + g0) = __halves2half2(
            __float2half_rn(v00 - __half2float(h00)),
            __float2half_rn(v01 - __half2float(h01)));
        *(__half2*)(Olo + g1) = __halves2half2(
            __float2half_rn(v10 - __half2float(h10)),
            __float2half_rn(v11 - __half2float(h11)));
    }
}

// ---------------------------------------------------------------------------
// Launch
// ---------------------------------------------------------------------------
extern "C" void kernel_launch(void* const* d_in, const int* in_sizes, int n_in,
                              void* d_out, int out_size)
{
    const float* query = (const float*)d_in[0];
    const float* key_t = (const float*)d_in[1];
    const float* value = (const float*)d_in[2];
    const float* Wq    = (const float*)d_in[3];
    const float* bq    = (const float*)d_in[4];
    const float* Wk    = (const float*)d_in[5];
    const float* bk    = (const float*)d_in[6];
    const float* Wv    = (const float*)d_in[7];
    const float* bv    = (const float*)d_in[8];
    const float* Wo    = (const float*)d_in[9];
    const float* bo    = (const float*)d_in[10];
    const float* noise = (const float*)d_in[11];
    float* out = (float*)d_out;

    __half *xh, *wh, *qh, *kh, *vh, *ch, *cl;
    cudaGetSymbolAddress((void**)&xh, g_xh);
    cudaGetSymbolAddress((void**)&wh, g_wh);
    cudaGetSymbolAddress((void**)&qh, g_qh);
    cudaGetSymbolAddress((void**)&kh, g_kh);
    cudaGetSymbolAddress((void**)&vh, g_vh);
    cudaGetSymbolAddress((void**)&ch, g_ch);
    cudaGetSymbolAddress((void**)&cl, g_cl);

    cudaFuncSetAttribute(gemm1_kernel,
                         cudaFuncAttributeMaxDynamicSharedMemorySize, GEMM1_SMEM);
    cudaFuncSetAttribute(gemm2_kernel,
                         cudaFuncAttributeMaxDynamicSharedMemorySize, GEMM2_SMEM);
    cudaFuncSetAttribute(attn_mma_kernel,
                         cudaFuncAttributeMaxDynamicSharedMemorySize, ATTN_SMEM);

    const size_t xTot = (size_t)MTOT * E_;
    const size_t wTot = (size_t)E_ * E_;
    const int cX = (int)((xTot / 8 + 255) / 256);
    const int cW = (int)((wTot / 8 + 255) / 256);
    dim3 gemmGrid(E_ / 128, MTOT / 128);   // (16, 64)

    // Q = query @ Wq^T + bq
    convert_h<<<cX, 256>>>(query, xh, xTot);
    convert_h<<<cW, 256>>>(Wq, wh, wTot);
    gemm1_kernel<<<gemmGrid, 256, GEMM1_SMEM>>>(xh, wh, bq, qh);

    // K = key_t @ Wk^T + bk
    convert_h<<<cX, 256>>>(key_t, xh, xTot);
    convert_h<<<cW, 256>>>(Wk, wh, wTot);
    gemm1_kernel<<<gemmGrid, 256, GEMM1_SMEM>>>(xh, wh, bk, kh);

    // V = value @ Wv^T + bv
    convert_h<<<cX, 256>>>(value, xh, xTot);
    convert_h<<<cW, 256>>>(Wv, wh, wTot);
    gemm1_kernel<<<gemmGrid, 256, GEMM1_SMEM>>>(xh, wh, bv, vh);

    // Attention + DP noise -> ctx hi/lo
    dim3 attnGrid(S_ / 128, H_, B_);       // (16, 16, 4)
    attn_mma_kernel<<<attnGrid, 256, ATTN_SMEM>>>(qh, kh, vh, noise, ch, cl);

    // out = ctx @ Wo^T + bo  (2-term: ctx exact, Wo rounded)
    convert_h<<<cW, 256>>>(Wo, wh, wTot);
    gemm2_kernel<<<gemmGrid, 256, GEMM2_SMEM>>>(ch, cl, wh, bo, out);
}